// round 3
// baseline (speedup 1.0000x reference)
#include <cuda_runtime.h>

// ---------------- problem constants ----------------
#define B_    4
#define C_    64
#define NA_   25
#define D_    128
#define H_    32
#define W_    32
#define S_    25600      // NA*H*W
#define NPOS_ 102400     // B*S
#define M_SF  1024
#define K_SF  800
#define M_AF  160
#define K_AF  5120
#define M_SA  160
#define K_SA  10240
#define NEGV  (-1e15f)

// ---------------- scratch (device globals; no allocation) ----------------
__device__ float g_q [B_*D_*S_];
__device__ float g_kv[B_*D_*S_];

__device__ float g_sfQ[B_*M_SF*K_SF];
__device__ float g_sfK[B_*M_SF*K_SF];
__device__ float g_sfO[B_*M_SF*K_SF];
__device__ float g_afQ[B_*M_AF*K_AF];
__device__ float g_afK[B_*M_AF*K_AF];
__device__ float g_afO[B_*M_AF*K_AF];
__device__ float g_saQ[B_*M_SA*K_SA];
__device__ float g_saK[B_*M_SA*K_SA];
__device__ float g_saO[B_*M_SA*K_SA];

__device__ float g_ivq_sf[B_*M_SF];
__device__ float g_ivk_sf[B_*M_SF];
__device__ float g_ivq_af[B_*M_AF];
__device__ float g_ivk_af[B_*M_AF];
__device__ float g_ivq_sa[B_*M_SA];
__device__ float g_ivk_sa[B_*M_SA];

__device__ float g_att[B_*M_SF*M_SF];   // reused by all three attentions (sequential)

__device__ float g_ct[NPOS_*D_];
__device__ float g_ln[NPOS_*D_];        // LN output; later reused as h2
__device__ float g_h1[NPOS_*D_];

// ---------------- 1) token projection: y[b,dc,s] = sum_c x[b,c,s]*W[c,dc] ----------------
template<int WHICH>   // 0: x_hf*W_in -> g_q ; 1: x_lf*W_kv -> g_kv
__global__ void k_tokens(const float* __restrict__ x, const float* __restrict__ Wm) {
    __shared__ float xs[C_][32];     // 8 KB
    __shared__ float ws[C_][D_];     // 32 KB
    float* y = (WHICH == 0) ? g_q : g_kv;
    int P0 = blockIdx.x * 32;
    int b  = P0 / S_;
    int s0 = P0 % S_;
    int t  = threadIdx.x;
    for (int i = t; i < C_*D_; i += 128) ws[i / D_][i % D_] = Wm[i];
    const float* xb = x + (size_t)b*C_*S_ + s0;
    for (int i = t; i < C_*32; i += 128) {
        int cc = i >> 5, pp = i & 31;
        xs[cc][pp] = xb[(size_t)cc*S_ + pp];
    }
    __syncthreads();
    int dc = t;          // 128 threads, one output channel each
    float acc[32];
    #pragma unroll
    for (int i = 0; i < 32; i++) acc[i] = 0.f;
    #pragma unroll 4
    for (int cc = 0; cc < C_; cc++) {
        float wv = ws[cc][dc];
        #pragma unroll
        for (int pp = 0; pp < 32; pp++) acc[pp] += wv * xs[cc][pp];
    }
    float* yb = y + ((size_t)b*D_ + dc)*S_ + s0;
    #pragma unroll
    for (int pp = 0; pp < 32; pp++) yb[pp] = acc[pp];
}

// ---------------- 2) fold gather + inverse L2 norms ----------------
// TYPE 0 sf: ch slice [0,32),  m=(ch,hh), k=(ww,uu,vv)  M=1024 K=800
// TYPE 1 af: ch slice [32,64), m=(ch,uu), k=(hh,vv,ww)  M=160  K=5120
// TYPE 2 sa: ch slice [64,128),m=(hh,uu), k=(ch,vv,ww)  M=160  K=10240
template<int TYPE>
__global__ void k_fold() {
    constexpr int MM  = TYPE==0 ? M_SF : (TYPE==1 ? M_AF : M_SA);
    constexpr int KK  = TYPE==0 ? K_SF : (TYPE==1 ? K_AF : K_SA);
    constexpr int OFF = TYPE==0 ? 0 : (TYPE==1 ? 32 : 64);
    int row = blockIdx.x;              // [0, B*MM)
    int isK = blockIdx.y;              // 0 = Q side, 1 = K side
    int b = row / MM, m = row % MM;
    const float* src = isK ? g_kv : g_q;
    float* dst; float* ivd;
    if (TYPE==0) { dst = isK ? g_sfK : g_sfQ; ivd = isK ? g_ivk_sf : g_ivq_sf; }
    else if (TYPE==1) { dst = isK ? g_afK : g_afQ; ivd = isK ? g_ivk_af : g_ivq_af; }
    else { dst = isK ? g_saK : g_saQ; ivd = isK ? g_ivk_sa : g_ivq_sa; }
    const float* base = src + ((size_t)b*D_ + OFF)*S_;
    float* drow = dst + (size_t)row*KK;
    int t = threadIdx.x;
    float ss = 0.f;
    if (TYPE == 0) {
        int ch = m >> 5, hh = m & 31;
        const float* bp = base + (size_t)ch*S_ + hh*W_;
        for (int kk = t; kk < KK; kk += 256) {       // kk = n*32 + ww (coalesced reads)
            int n = kk >> 5, ww = kk & 31;
            float v = bp[n*(H_*W_) + ww];
            drow[ww*25 + n] = v;
            ss += v*v;
        }
    } else if (TYPE == 1) {
        int ch = m / 5, uu = m % 5;
        const float* bp = base + (size_t)ch*S_;
        for (int k = t; k < KK; k += 256) {          // k = (hh*5+vv)*32 + ww
            int hh = k / 160, vv = (k >> 5) % 5, ww = k & 31;
            int n = uu*5 + vv;
            float v = bp[n*(H_*W_) + hh*W_ + ww];
            drow[k] = v;
            ss += v*v;
        }
    } else {
        int hh = m / 5, uu = m % 5;
        for (int k = t; k < KK; k += 256) {          // k = (ch*5+vv)*32 + ww
            int ch = k / 160, vv = (k >> 5) % 5, ww = k & 31;
            int n = uu*5 + vv;
            float v = base[(size_t)ch*S_ + n*(H_*W_) + hh*W_ + ww];
            drow[k] = v;
            ss += v*v;
        }
    }
    __shared__ float red[256];
    red[t] = ss; __syncthreads();
    for (int st = 128; st > 0; st >>= 1) { if (t < st) red[t] += red[t + st]; __syncthreads(); }
    if (t == 0) ivd[row] = 1.f / fmaxf(sqrtf(red[0]), 1e-12f);
}

// ---------------- 3) attention scores: S = (Q K^T) * ivq*ivk, causal mask ----------------
template<int TYPE>
__global__ void k_score() {
    constexpr int MM = TYPE==0 ? M_SF : (TYPE==1 ? M_AF : M_SA);
    constexpr int KK = TYPE==0 ? K_SF : (TYPE==1 ? K_AF : K_SA);
    const float* Qf = TYPE==0 ? g_sfQ : (TYPE==1 ? g_afQ : g_saQ);
    const float* Kf = TYPE==0 ? g_sfK : (TYPE==1 ? g_afK : g_saK);
    const float* ivq = TYPE==0 ? g_ivq_sf : (TYPE==1 ? g_ivq_af : g_ivq_sa);
    const float* ivk = TYPE==0 ? g_ivk_sf : (TYPE==1 ? g_ivk_af : g_ivk_sa);
    int b = blockIdx.z, m0 = blockIdx.y*64, n0 = blockIdx.x*64;
    int t = threadIdx.x, tn = t & 15, tm = t >> 4;
    float* att = g_att + (size_t)b*MM*MM;
    if (n0 > m0 + 63) {                          // fully masked tile
        #pragma unroll
        for (int i = 0; i < 4; i++) {
            int m = m0 + tm*4 + i; if (m >= MM) continue;
            #pragma unroll
            for (int j = 0; j < 4; j++) {
                int n = n0 + tn*4 + j; if (n >= MM) continue;
                att[(size_t)m*MM + n] = NEGV;
            }
        }
        return;
    }
    __shared__ __align__(16) float As[16][64];
    __shared__ __align__(16) float Bs[16][64];
    const float* Ab = Qf + (size_t)b*MM*KK;
    const float* Bb = Kf + (size_t)b*MM*KK;
    int lr = t >> 2, lc = (t & 3) << 2;
    float acc[4][4] = {};
    for (int k0 = 0; k0 < KK; k0 += 16) {
        float4 av = make_float4(0,0,0,0), bv = make_float4(0,0,0,0);
        if (m0 + lr < MM) av = *(const float4*)(Ab + (size_t)(m0+lr)*KK + k0 + lc);
        if (n0 + lr < MM) bv = *(const float4*)(Bb + (size_t)(n0+lr)*KK + k0 + lc);
        __syncthreads();
        As[lc+0][lr]=av.x; As[lc+1][lr]=av.y; As[lc+2][lr]=av.z; As[lc+3][lr]=av.w;
        Bs[lc+0][lr]=bv.x; Bs[lc+1][lr]=bv.y; Bs[lc+2][lr]=bv.z; Bs[lc+3][lr]=bv.w;
        __syncthreads();
        #pragma unroll
        for (int kk = 0; kk < 16; kk++) {
            float4 a = *(const float4*)&As[kk][tm << 2];
            float4 bq = *(const float4*)&Bs[kk][tn << 2];
            acc[0][0]+=a.x*bq.x; acc[0][1]+=a.x*bq.y; acc[0][2]+=a.x*bq.z; acc[0][3]+=a.x*bq.w;
            acc[1][0]+=a.y*bq.x; acc[1][1]+=a.y*bq.y; acc[1][2]+=a.y*bq.z; acc[1][3]+=a.y*bq.w;
            acc[2][0]+=a.z*bq.x; acc[2][1]+=a.z*bq.y; acc[2][2]+=a.z*bq.z; acc[2][3]+=a.z*bq.w;
            acc[3][0]+=a.w*bq.x; acc[3][1]+=a.w*bq.y; acc[3][2]+=a.w*bq.z; acc[3][3]+=a.w*bq.w;
        }
    }
    #pragma unroll
    for (int i = 0; i < 4; i++) {
        int m = m0 + (tm<<2) + i; if (m >= MM) continue;
        float qn = ivq[b*MM + m];
        #pragma unroll
        for (int j = 0; j < 4; j++) {
            int n = n0 + (tn<<2) + j; if (n >= MM) continue;
            float v = acc[i][j] * qn * ivk[b*MM + n];
            if (n > m) v = NEGV;
            att[(size_t)m*MM + n] = v;
        }
    }
}

// ---------------- 4) row softmax over masked scores ----------------
template<int TYPE>
__global__ void k_softmax() {
    constexpr int MM = TYPE==0 ? M_SF : (TYPE==1 ? M_AF : M_SA);
    float* p = g_att + (size_t)blockIdx.x * MM;
    int t = threadIdx.x;
    __shared__ float red[256];
    float mx = -3.4e38f;
    for (int k = t; k < MM; k += 256) mx = fmaxf(mx, p[k]);
    red[t] = mx; __syncthreads();
    for (int st = 128; st > 0; st >>= 1) { if (t < st) red[t] = fmaxf(red[t], red[t+st]); __syncthreads(); }
    mx = red[0]; __syncthreads();
    float s = 0.f;
    for (int k = t; k < MM; k += 256) { float e = expf(p[k] - mx); p[k] = e; s += e; }
    red[t] = s; __syncthreads();
    for (int st = 128; st > 0; st >>= 1) { if (t < st) red[t] += red[t+st]; __syncthreads(); }
    float inv = 1.f / red[0];
    for (int k = t; k < MM; k += 256) p[k] *= inv;
}

// ---------------- 5) O = P @ V (V = raw K fold) ----------------
template<int TYPE>
__global__ void k_pv() {
    constexpr int MM = TYPE==0 ? M_SF : (TYPE==1 ? M_AF : M_SA);
    constexpr int KK = TYPE==0 ? K_SF : (TYPE==1 ? K_AF : K_SA);
    const float* V = TYPE==0 ? g_sfK : (TYPE==1 ? g_afK : g_saK);
    float* O = TYPE==0 ? g_sfO : (TYPE==1 ? g_afO : g_saO);
    int b = blockIdx.z, m0 = blockIdx.y*64, k0 = blockIdx.x*64;
    int t = threadIdx.x, tn = t & 15, tm = t >> 4;
    const float* Pb = g_att + (size_t)b*MM*MM;
    const float* Vb = V + (size_t)b*MM*KK;
    __shared__ __align__(16) float As[16][64];   // [n][m]
    __shared__ __align__(16) float Bs[16][64];   // [n][k]
    int lr = t >> 2, lc = (t & 3) << 2;          // A-tile loader
    int br = t >> 4, bc = (t & 15) << 2;         // B-tile loader
    float acc[4][4] = {};
    for (int n0 = 0; n0 < MM; n0 += 16) {
        float4 av = make_float4(0,0,0,0), bv = make_float4(0,0,0,0);
        if (m0 + lr < MM) av = *(const float4*)(Pb + (size_t)(m0+lr)*MM + n0 + lc);
        if (k0 + bc < KK) bv = *(const float4*)(Vb + (size_t)(n0+br)*KK + k0 + bc);
        __syncthreads();
        As[lc+0][lr]=av.x; As[lc+1][lr]=av.y; As[lc+2][lr]=av.z; As[lc+3][lr]=av.w;
        *(float4*)&Bs[br][bc] = bv;
        __syncthreads();
        #pragma unroll
        for (int nn = 0; nn < 16; nn++) {
            float4 a = *(const float4*)&As[nn][tm << 2];
            float4 bq = *(const float4*)&Bs[nn][tn << 2];
            acc[0][0]+=a.x*bq.x; acc[0][1]+=a.x*bq.y; acc[0][2]+=a.x*bq.z; acc[0][3]+=a.x*bq.w;
            acc[1][0]+=a.y*bq.x; acc[1][1]+=a.y*bq.y; acc[1][2]+=a.y*bq.z; acc[1][3]+=a.y*bq.w;
            acc[2][0]+=a.z*bq.x; acc[2][1]+=a.z*bq.y; acc[2][2]+=a.z*bq.z; acc[2][3]+=a.z*bq.w;
            acc[3][0]+=a.w*bq.x; acc[3][1]+=a.w*bq.y; acc[3][2]+=a.w*bq.z; acc[3][3]+=a.w*bq.w;
        }
    }
    #pragma unroll
    for (int i = 0; i < 4; i++) {
        int m = m0 + (tm<<2) + i; if (m >= MM) continue;
        #pragma unroll
        for (int j = 0; j < 4; j++) {
            int k = k0 + (tn<<2) + j; if (k >= KK) continue;
            O[((size_t)b*MM + m)*KK + k] = acc[i][j];
        }
    }
}

// ---------------- 6) unfold + residual -> ct[token][d] ----------------
__global__ void k_combine() {
    int i = blockIdx.x * 256 + threadIdx.x;    // over NPOS*D
    int dc = i & 127;
    int T  = i >> 7;
    int ww = T & 31, hh = (T >> 5) & 31;
    int bn = T >> 10;          // b*25 + n
    int b = bn / 25, n = bn % 25;
    int uu = n / 5, vv = n % 5;
    float r = g_kv[((size_t)b*D_ + dc)*S_ + n*(H_*W_) + hh*W_ + ww];
    float o;
    if (dc < 32) {
        int m = dc*32 + hh, k = ww*25 + n;
        o = g_sfO[((size_t)b*M_SF + m)*K_SF + k];
    } else if (dc < 64) {
        int m = (dc-32)*5 + uu, k = (hh*5 + vv)*32 + ww;
        o = g_afO[((size_t)b*M_AF + m)*K_AF + k];
    } else {
        int m = hh*5 + uu, k = ((dc-64)*5 + vv)*32 + ww;
        o = g_saO[((size_t)b*M_SA + m)*K_SA + k];
    }
    g_ct[i] = o + r;
}

// ---------------- 7) LayerNorm (warp per token) ----------------
__global__ void k_ln(const float* __restrict__ gamma, const float* __restrict__ beta) {
    int T = blockIdx.x * 8 + (threadIdx.x >> 5);
    int lane = threadIdx.x & 31;
    const float* row = g_ct + (size_t)T * D_;
    float4 v = *(const float4*)(row + lane*4);
    float s = v.x + v.y + v.z + v.w;
    #pragma unroll
    for (int o = 16; o > 0; o >>= 1) s += __shfl_xor_sync(0xffffffffu, s, o);
    float mu = s * (1.f / 128.f);
    float cx = v.x - mu, cy = v.y - mu, cz = v.z - mu, cw = v.w - mu;
    float sq = cx*cx + cy*cy + cz*cz + cw*cw;
    #pragma unroll
    for (int o = 16; o > 0; o >>= 1) sq += __shfl_xor_sync(0xffffffffu, sq, o);
    float inv = rsqrtf(sq * (1.f / 128.f) + 1e-5f);
    float4 gmv = *(const float4*)(gamma + lane*4);
    float4 bev = *(const float4*)(beta + lane*4);
    float4 o4;
    o4.x = cx*inv*gmv.x + bev.x;
    o4.y = cy*inv*gmv.y + bev.y;
    o4.z = cz*inv*gmv.z + bev.z;
    o4.w = cw*inv*gmv.w + bev.w;
    *(float4*)(g_ln + (size_t)T*D_ + lane*4) = o4;
}

// ---------------- 8) MLP gemms over [NPOS x 128] ----------------
// MODE 0: h1 = relu(ln @ W_m1)   MODE 1: ln <- h1 @ W_m2 (reuse buffer)
// MODE 2: out = (ln+ct) @ W_out (scatter to output layout)
template<int MODE>
__global__ void k_mlp(const float* __restrict__ Wm, float* __restrict__ outp) {
    constexpr int NOUT = (MODE == 2) ? 64 : 128;
    const float* A  = (MODE == 1) ? g_h1 : g_ln;
    const float* A2 = (MODE == 2) ? g_ct : nullptr;
    int m0 = blockIdx.y * 64, n0 = blockIdx.x * 64;
    int t = threadIdx.x, tn = t & 15, tm = t >> 4;
    __shared__ __align__(16) float As[16][64];
    __shared__ __align__(16) float Bs[16][64];
    int lr = t >> 2, lc = (t & 3) << 2;
    int br = t >> 4, bc = (t & 15) << 2;
    float acc[4][4] = {};
    for (int k0 = 0; k0 < 128; k0 += 16) {
        float4 av = *(const float4*)(A + (size_t)(m0+lr)*D_ + k0 + lc);
        if (MODE == 2) {
            float4 a2 = *(const float4*)(A2 + (size_t)(m0+lr)*D_ + k0 + lc);
            av.x += a2.x; av.y += a2.y; av.z += a2.z; av.w += a2.w;
        }
        float4 bv = *(const float4*)(Wm + (size_t)(k0+br)*NOUT + n0 + bc);
        __syncthreads();
        As[lc+0][lr]=av.x; As[lc+1][lr]=av.y; As[lc+2][lr]=av.z; As[lc+3][lr]=av.w;
        *(float4*)&Bs[br][bc] = bv;
        __syncthreads();
        #pragma unroll
        for (int kk = 0; kk < 16; kk++) {
            float4 a = *(const float4*)&As[kk][tm << 2];
            float4 bq = *(const float4*)&Bs[kk][tn << 2];
            acc[0][0]+=a.x*bq.x; acc[0][1]+=a.x*bq.y; acc[0][2]+=a.x*bq.z; acc[0][3]+=a.x*bq.w;
            acc[1][0]+=a.y*bq.x; acc[1][1]+=a.y*bq.y; acc[1][2]+=a.y*bq.z; acc[1][3]+=a.y*bq.w;
            acc[2][0]+=a.z*bq.x; acc[2][1]+=a.z*bq.y; acc[2][2]+=a.z*bq.z; acc[2][3]+=a.z*bq.w;
            acc[3][0]+=a.w*bq.x; acc[3][1]+=a.w*bq.y; acc[3][2]+=a.w*bq.z; acc[3][3]+=a.w*bq.w;
        }
    }
    #pragma unroll
    for (int i = 0; i < 4; i++) {
        int m = m0 + (tm<<2) + i;
        #pragma unroll
        for (int j = 0; j < 4; j++) {
            int nn = n0 + (tn<<2) + j;
            float v = acc[i][j];
            if (MODE == 0) {
                g_h1[(size_t)m*D_ + nn] = fmaxf(v, 0.f);
            } else if (MODE == 1) {
                g_ln[(size_t)m*D_ + nn] = v;
            } else {
                int ww = m & 31, hh = (m >> 5) & 31;
                int bn = m >> 10;
                int b = bn / 25, na = bn % 25;
                outp[((size_t)b*C_ + nn)*S_ + na*(H_*W_) + hh*W_ + ww] = v;
            }
        }
    }
}

// ---------------- launch ----------------
extern "C" void kernel_launch(void* const* d_in, const int* in_sizes, int n_in,
                              void* d_out, int out_size) {
    const float* x_lf = (const float*)d_in[0];
    const float* x_hf = (const float*)d_in[1];
    const float* W_in = (const float*)d_in[2];
    const float* W_kv = (const float*)d_in[3];
    const float* ln_g = (const float*)d_in[4];
    const float* ln_b = (const float*)d_in[5];
    const float* W_m1 = (const float*)d_in[6];
    const float* W_m2 = (const float*)d_in[7];
    const float* W_ot = (const float*)d_in[8];
    float* out = (float*)d_out;

    k_tokens<0><<<NPOS_/32, 128>>>(x_hf, W_in);
    k_tokens<1><<<NPOS_/32, 128>>>(x_lf, W_kv);

    // sf attention
    k_fold<0><<<dim3(B_*M_SF, 2), 256>>>();
    k_score<0><<<dim3(M_SF/64, M_SF/64, B_), 256>>>();
    k_softmax<0><<<B_*M_SF, 256>>>();
    k_pv<0><<<dim3((K_SF+63)/64, M_SF/64, B_), 256>>>();

    // af attention
    k_fold<1><<<dim3(B_*M_AF, 2), 256>>>();
    k_score<1><<<dim3((M_AF+63)/64, (M_AF+63)/64, B_), 256>>>();
    k_softmax<1><<<B_*M_AF, 256>>>();
    k_pv<1><<<dim3(K_AF/64, (M_AF+63)/64, B_), 256>>>();

    // sa attention
    k_fold<2><<<dim3(B_*M_SA, 2), 256>>>();
    k_score<2><<<dim3((M_SA+63)/64, (M_SA+63)/64, B_), 256>>>();
    k_softmax<2><<<B_*M_SA, 256>>>();
    k_pv<2><<<dim3(K_SA/64, (M_SA+63)/64, B_), 256>>>();

    // combine + LN + MLP + out
    k_combine<<<(NPOS_*D_)/256, 256>>>();
    k_ln<<<NPOS_/8, 256>>>(ln_g, ln_b);
    k_mlp<0><<<dim3(2, NPOS_/64), 256>>>(W_m1, nullptr);
    k_mlp<1><<<dim3(2, NPOS_/64), 256>>>(W_m2, nullptr);
    k_mlp<2><<<dim3(1, NPOS_/64), 256>>>(W_ot, out);
}

// round 4
// speedup vs baseline: 1.1507x; 1.1507x over previous
#include <cuda_runtime.h>

// ---------------- problem constants ----------------
#define B_    4
#define C_    64
#define NA_   25
#define D_    128
#define H_    32
#define W_    32
#define S_    25600      // NA*H*W
#define NPOS_ 102400     // B*S
#define M_SF  1024
#define K_SF  800
#define M_AF  160
#define K_AF  5120
#define M_SA  160
#define K_SA  10240
#define NEGV  (-1e15f)

// ---------------- scratch (device globals; no allocation) ----------------
__device__ float g_q [B_*D_*S_];
__device__ float g_kv[B_*D_*S_];

__device__ float g_sfQ[B_*M_SF*K_SF];
__device__ float g_sfK[B_*M_SF*K_SF];
__device__ float g_sfO[B_*M_SF*K_SF];
__device__ float g_afQ[B_*M_AF*K_AF];
__device__ float g_afK[B_*M_AF*K_AF];
__device__ float g_afO[B_*M_AF*K_AF];
__device__ float g_saQ[B_*M_SA*K_SA];
__device__ float g_saK[B_*M_SA*K_SA];
__device__ float g_saO[B_*M_SA*K_SA];

__device__ float g_ivq_sf[B_*M_SF];
__device__ float g_ivk_sf[B_*M_SF];
__device__ float g_ivq_af[B_*M_AF];
__device__ float g_ivk_af[B_*M_AF];
__device__ float g_ivq_sa[B_*M_SA];
__device__ float g_ivk_sa[B_*M_SA];

__device__ float g_att[B_*M_SF*M_SF];   // reused by all three attentions (sequential)

__device__ float g_ct[NPOS_*D_];
__device__ float g_ln[NPOS_*D_];        // LN output; later reused as h2
__device__ float g_h1[NPOS_*D_];

// ===================================================================
// 1) token projection as 128x128x64 GEMM: y[b,dc,s] = sum_c x[b,c,s]*W[c,dc]
//    A = x (already k-major across s: As needs [c][s] — direct loads, no transpose)
// ===================================================================
template<int WHICH>   // 0: x_hf*W_in -> g_q ; 1: x_lf*W_kv -> g_kv
__global__ __launch_bounds__(256) void k_tokens_big(const float* __restrict__ x,
                                                    const float* __restrict__ Wm) {
    float* y = (WHICH == 0) ? g_q : g_kv;
    int m0 = blockIdx.x * 128;          // position tile (within one b: S_ % 128 == 0)
    int b  = m0 / S_;
    int s0 = m0 % S_;
    const float* xb = x + (size_t)b*C_*S_;
    __shared__ __align__(16) float As[8][132];
    __shared__ __align__(16) float Bs[8][132];
    int t = threadIdx.x, tx = t & 15, ty = t >> 4;
    int crow = t >> 5, ccol = (t & 31) * 4;
    float acc[8][8] = {};
    for (int k0 = 0; k0 < C_; k0 += 8) {
        float4 av = *(const float4*)(xb + (size_t)(k0+crow)*S_ + s0 + ccol);
        float4 bv = *(const float4*)(Wm + (size_t)(k0+crow)*D_ + ccol);
        __syncthreads();
        *(float4*)&As[crow][ccol] = av;
        *(float4*)&Bs[crow][ccol] = bv;
        __syncthreads();
        #pragma unroll
        for (int kk = 0; kk < 8; kk++) {
            float ar[8], br[8];
            *(float4*)&ar[0] = *(const float4*)&As[kk][ty*4];
            *(float4*)&ar[4] = *(const float4*)&As[kk][ty*4+64];
            *(float4*)&br[0] = *(const float4*)&Bs[kk][tx*4];
            *(float4*)&br[4] = *(const float4*)&Bs[kk][tx*4+64];
            #pragma unroll
            for (int i = 0; i < 8; i++)
                #pragma unroll
                for (int j = 0; j < 8; j++) acc[i][j] += ar[i]*br[j];
        }
    }
    #pragma unroll
    for (int j = 0; j < 8; j++) {
        int dc = tx*4 + (j < 4 ? j : j + 60);
        float* yb = y + ((size_t)b*D_ + dc)*S_ + s0;
        *(float4*)(yb + ty*4)      = make_float4(acc[0][j], acc[1][j], acc[2][j], acc[3][j]);
        *(float4*)(yb + 64 + ty*4) = make_float4(acc[4][j], acc[5][j], acc[6][j], acc[7][j]);
    }
}

// ---------------- 2) fold gather + inverse L2 norms ----------------
// TYPE 0 sf: ch slice [0,32),  m=(ch,hh), k=(n,ww) [permuted; coalesced]  M=1024 K=800
// TYPE 1 af: ch slice [32,64), m=(ch,uu), k=(hh,vv,ww)  M=160  K=5120
// TYPE 2 sa: ch slice [64,128),m=(hh,uu), k=(ch,vv,ww)  M=160  K=10240
template<int TYPE>
__global__ void k_fold() {
    constexpr int MM  = TYPE==0 ? M_SF : (TYPE==1 ? M_AF : M_SA);
    constexpr int KK  = TYPE==0 ? K_SF : (TYPE==1 ? K_AF : K_SA);
    constexpr int OFF = TYPE==0 ? 0 : (TYPE==1 ? 32 : 64);
    int row = blockIdx.x;              // [0, B*MM)
    int isK = blockIdx.y;              // 0 = Q side, 1 = K side
    int b = row / MM, m = row % MM;
    const float* src = isK ? g_kv : g_q;
    float* dst; float* ivd;
    if (TYPE==0) { dst = isK ? g_sfK : g_sfQ; ivd = isK ? g_ivk_sf : g_ivq_sf; }
    else if (TYPE==1) { dst = isK ? g_afK : g_afQ; ivd = isK ? g_ivk_af : g_ivq_af; }
    else { dst = isK ? g_saK : g_saQ; ivd = isK ? g_ivk_sa : g_ivq_sa; }
    const float* base = src + ((size_t)b*D_ + OFF)*S_;
    float* drow = dst + (size_t)row*KK;
    int t = threadIdx.x;
    float ss = 0.f;
    if (TYPE == 0) {
        int ch = m >> 5, hh = m & 31;
        const float* bp = base + (size_t)ch*S_ + hh*W_;
        for (int kk = t; kk < KK; kk += 256) {       // kk = n*32 + ww (coalesced in AND out)
            int n = kk >> 5, ww = kk & 31;
            float v = bp[n*(H_*W_) + ww];
            drow[kk] = v;
            ss += v*v;
        }
    } else if (TYPE == 1) {
        int ch = m / 5, uu = m % 5;
        const float* bp = base + (size_t)ch*S_;
        for (int k = t; k < KK; k += 256) {          // k = (hh*5+vv)*32 + ww
            int hh = k / 160, vv = (k >> 5) % 5, ww = k & 31;
            int n = uu*5 + vv;
            float v = bp[n*(H_*W_) + hh*W_ + ww];
            drow[k] = v;
            ss += v*v;
        }
    } else {
        int hh = m / 5, uu = m % 5;
        for (int k = t; k < KK; k += 256) {          // k = (ch*5+vv)*32 + ww
            int ch = k / 160, vv = (k >> 5) % 5, ww = k & 31;
            int n = uu*5 + vv;
            float v = base[(size_t)ch*S_ + n*(H_*W_) + hh*W_ + ww];
            drow[k] = v;
            ss += v*v;
        }
    }
    __shared__ float red[256];
    red[t] = ss; __syncthreads();
    for (int st = 128; st > 0; st >>= 1) { if (t < st) red[t] += red[t + st]; __syncthreads(); }
    if (t == 0) ivd[row] = 1.f / fmaxf(sqrtf(red[0]), 1e-12f);
}

// ===================================================================
// 3a) SF scores: 128x128 tile, 8x8 micro, NT. Skips masked tiles (no fill).
// ===================================================================
__global__ __launch_bounds__(256) void k_score_sf() {
    int b = blockIdx.z, m0 = blockIdx.y*128, n0 = blockIdx.x*128;
    if (n0 > m0 + 127) return;                   // never read downstream
    const float* Ab = g_sfQ + (size_t)b*M_SF*K_SF;
    const float* Bb = g_sfK + (size_t)b*M_SF*K_SF;
    __shared__ __align__(16) float As[8][132];
    __shared__ __align__(16) float Bs[8][132];
    int t = threadIdx.x, tx = t & 15, ty = t >> 4;
    int lrow = t >> 1, lcol = (t & 1) * 4;
    float acc[8][8] = {};
    for (int k0 = 0; k0 < K_SF; k0 += 8) {
        float4 av = *(const float4*)(Ab + (size_t)(m0+lrow)*K_SF + k0 + lcol);
        float4 bv = *(const float4*)(Bb + (size_t)(n0+lrow)*K_SF + k0 + lcol);
        __syncthreads();
        As[lcol+0][lrow]=av.x; As[lcol+1][lrow]=av.y; As[lcol+2][lrow]=av.z; As[lcol+3][lrow]=av.w;
        Bs[lcol+0][lrow]=bv.x; Bs[lcol+1][lrow]=bv.y; Bs[lcol+2][lrow]=bv.z; Bs[lcol+3][lrow]=bv.w;
        __syncthreads();
        #pragma unroll
        for (int kk = 0; kk < 8; kk++) {
            float ar[8], br[8];
            *(float4*)&ar[0] = *(const float4*)&As[kk][ty*4];
            *(float4*)&ar[4] = *(const float4*)&As[kk][ty*4+64];
            *(float4*)&br[0] = *(const float4*)&Bs[kk][tx*4];
            *(float4*)&br[4] = *(const float4*)&Bs[kk][tx*4+64];
            #pragma unroll
            for (int i = 0; i < 8; i++)
                #pragma unroll
                for (int j = 0; j < 8; j++) acc[i][j] += ar[i]*br[j];
        }
    }
    float* att = g_att + (size_t)b*M_SF*M_SF;
    const float* ivq = g_ivq_sf + b*M_SF;
    const float* ivk = g_ivk_sf + b*M_SF;
    #pragma unroll
    for (int i = 0; i < 8; i++) {
        int m = m0 + ty*4 + (i < 4 ? i : i + 60);
        float qn = ivq[m];
        #pragma unroll
        for (int j = 0; j < 8; j++) {
            int n = n0 + tx*4 + (j < 4 ? j : j + 60);
            float v = acc[i][j] * qn * ivk[n];
            att[(size_t)m*M_SF + n] = (n > m) ? NEGV : v;
        }
    }
}

// ===================================================================
// 3b) small scores for af/sa (64x64 tile, 4x4 micro) — unchanged path
// ===================================================================
template<int TYPE>
__global__ void k_score() {
    constexpr int MM = TYPE==1 ? M_AF : M_SA;
    constexpr int KK = TYPE==1 ? K_AF : K_SA;
    const float* Qf = TYPE==1 ? g_afQ : g_saQ;
    const float* Kf = TYPE==1 ? g_afK : g_saK;
    const float* ivq = TYPE==1 ? g_ivq_af : g_ivq_sa;
    const float* ivk = TYPE==1 ? g_ivk_af : g_ivk_sa;
    int b = blockIdx.z, m0 = blockIdx.y*64, n0 = blockIdx.x*64;
    int t = threadIdx.x, tn = t & 15, tm = t >> 4;
    float* att = g_att + (size_t)b*MM*MM;
    if (n0 > m0 + 63) {
        #pragma unroll
        for (int i = 0; i < 4; i++) {
            int m = m0 + tm*4 + i; if (m >= MM) continue;
            #pragma unroll
            for (int j = 0; j < 4; j++) {
                int n = n0 + tn*4 + j; if (n >= MM) continue;
                att[(size_t)m*MM + n] = NEGV;
            }
        }
        return;
    }
    __shared__ __align__(16) float As[16][64];
    __shared__ __align__(16) float Bs[16][64];
    const float* Ab = Qf + (size_t)b*MM*KK;
    const float* Bb = Kf + (size_t)b*MM*KK;
    int lr = t >> 2, lc = (t & 3) << 2;
    float acc[4][4] = {};
    for (int k0 = 0; k0 < KK; k0 += 16) {
        float4 av = make_float4(0,0,0,0), bv = make_float4(0,0,0,0);
        if (m0 + lr < MM) av = *(const float4*)(Ab + (size_t)(m0+lr)*KK + k0 + lc);
        if (n0 + lr < MM) bv = *(const float4*)(Bb + (size_t)(n0+lr)*KK + k0 + lc);
        __syncthreads();
        As[lc+0][lr]=av.x; As[lc+1][lr]=av.y; As[lc+2][lr]=av.z; As[lc+3][lr]=av.w;
        Bs[lc+0][lr]=bv.x; Bs[lc+1][lr]=bv.y; Bs[lc+2][lr]=bv.z; Bs[lc+3][lr]=bv.w;
        __syncthreads();
        #pragma unroll
        for (int kk = 0; kk < 16; kk++) {
            float4 a = *(const float4*)&As[kk][tm << 2];
            float4 bq = *(const float4*)&Bs[kk][tn << 2];
            acc[0][0]+=a.x*bq.x; acc[0][1]+=a.x*bq.y; acc[0][2]+=a.x*bq.z; acc[0][3]+=a.x*bq.w;
            acc[1][0]+=a.y*bq.x; acc[1][1]+=a.y*bq.y; acc[1][2]+=a.y*bq.z; acc[1][3]+=a.y*bq.w;
            acc[2][0]+=a.z*bq.x; acc[2][1]+=a.z*bq.y; acc[2][2]+=a.z*bq.z; acc[2][3]+=a.z*bq.w;
            acc[3][0]+=a.w*bq.x; acc[3][1]+=a.w*bq.y; acc[3][2]+=a.w*bq.z; acc[3][3]+=a.w*bq.w;
        }
    }
    #pragma unroll
    for (int i = 0; i < 4; i++) {
        int m = m0 + (tm<<2) + i; if (m >= MM) continue;
        float qn = ivq[b*MM + m];
        #pragma unroll
        for (int j = 0; j < 4; j++) {
            int n = n0 + (tn<<2) + j; if (n >= MM) continue;
            float v = acc[i][j] * qn * ivk[b*MM + n];
            if (n > m) v = NEGV;
            att[(size_t)m*MM + n] = v;
        }
    }
}

// ---------------- 4) row softmax; TYPE0 limits row to its diagonal tile ----------------
template<int TYPE>
__global__ void k_softmax() {
    constexpr int MM = TYPE==0 ? M_SF : (TYPE==1 ? M_AF : M_SA);
    float* p = g_att + (size_t)blockIdx.x * MM;
    int m = blockIdx.x % MM;
    int LIM = (TYPE==0) ? (((m >> 7) + 1) << 7) : MM;   // sf: only up to diag tile end
    int t = threadIdx.x;
    __shared__ float red[256];
    float mx = -3.4e38f;
    for (int k = t; k < LIM; k += 256) mx = fmaxf(mx, p[k]);
    red[t] = mx; __syncthreads();
    for (int st = 128; st > 0; st >>= 1) { if (t < st) red[t] = fmaxf(red[t], red[t+st]); __syncthreads(); }
    mx = red[0]; __syncthreads();
    float s = 0.f;
    for (int k = t; k < LIM; k += 256) { float e = expf(p[k] - mx); p[k] = e; s += e; }
    red[t] = s; __syncthreads();
    for (int st = 128; st > 0; st >>= 1) { if (t < st) red[t] += red[t+st]; __syncthreads(); }
    float inv = 1.f / red[0];
    for (int k = t; k < LIM; k += 256) p[k] *= inv;
}

// ===================================================================
// 5a) SF O = P @ V : 128x128 tile, 8x8 micro, causal bound on reduction
// ===================================================================
__global__ __launch_bounds__(256) void k_pv_sf() {
    int b = blockIdx.z, m0 = blockIdx.y*128, k0 = blockIdx.x*128;
    const float* Pb = g_att + (size_t)b*M_SF*M_SF;
    const float* Vb = g_sfK + (size_t)b*M_SF*K_SF;
    __shared__ __align__(16) float As[8][132];
    __shared__ __align__(16) float Bs[8][132];
    int t = threadIdx.x, tx = t & 15, ty = t >> 4;
    int lrow = t >> 1, lcol = (t & 1) * 4;      // P loader (transposed store)
    int vrow = t >> 5, vcol = (t & 31) * 4;     // V loader (direct)
    bool bval = (k0 + vcol) < K_SF;
    float acc[8][8] = {};
    int NLIM = m0 + 128;                        // P is exactly 0 beyond this
    for (int n0 = 0; n0 < NLIM; n0 += 8) {
        float4 av = *(const float4*)(Pb + (size_t)(m0+lrow)*M_SF + n0 + lcol);
        float4 bv = make_float4(0,0,0,0);
        if (bval) bv = *(const float4*)(Vb + (size_t)(n0+vrow)*K_SF + k0 + vcol);
        __syncthreads();
        As[lcol+0][lrow]=av.x; As[lcol+1][lrow]=av.y; As[lcol+2][lrow]=av.z; As[lcol+3][lrow]=av.w;
        *(float4*)&Bs[vrow][vcol] = bv;
        __syncthreads();
        #pragma unroll
        for (int kk = 0; kk < 8; kk++) {
            float ar[8], br[8];
            *(float4*)&ar[0] = *(const float4*)&As[kk][ty*4];
            *(float4*)&ar[4] = *(const float4*)&As[kk][ty*4+64];
            *(float4*)&br[0] = *(const float4*)&Bs[kk][tx*4];
            *(float4*)&br[4] = *(const float4*)&Bs[kk][tx*4+64];
            #pragma unroll
            for (int i = 0; i < 8; i++)
                #pragma unroll
                for (int j = 0; j < 8; j++) acc[i][j] += ar[i]*br[j];
        }
    }
    float* O = g_sfO + (size_t)b*M_SF*K_SF;
    #pragma unroll
    for (int i = 0; i < 8; i++) {
        int m = m0 + ty*4 + (i < 4 ? i : i + 60);
        int c0 = k0 + tx*4, c1 = c0 + 64;
        if (c0 < K_SF)
            *(float4*)(O + (size_t)m*K_SF + c0) = make_float4(acc[i][0],acc[i][1],acc[i][2],acc[i][3]);
        if (c1 < K_SF)
            *(float4*)(O + (size_t)m*K_SF + c1) = make_float4(acc[i][4],acc[i][5],acc[i][6],acc[i][7]);
    }
}

// ---------------- 5b) small P@V for af/sa (unchanged) ----------------
template<int TYPE>
__global__ void k_pv() {
    constexpr int MM = TYPE==1 ? M_AF : M_SA;
    constexpr int KK = TYPE==1 ? K_AF : K_SA;
    const float* V = TYPE==1 ? g_afK : g_saK;
    float* O = TYPE==1 ? g_afO : g_saO;
    int b = blockIdx.z, m0 = blockIdx.y*64, k0 = blockIdx.x*64;
    int t = threadIdx.x, tn = t & 15, tm = t >> 4;
    const float* Pb = g_att + (size_t)b*MM*MM;
    const float* Vb = V + (size_t)b*MM*KK;
    __shared__ __align__(16) float As[16][64];
    __shared__ __align__(16) float Bs[16][64];
    int lr = t >> 2, lc = (t & 3) << 2;
    int br = t >> 4, bc = (t & 15) << 2;
    float acc[4][4] = {};
    for (int n0 = 0; n0 < MM; n0 += 16) {
        float4 av = make_float4(0,0,0,0), bv = make_float4(0,0,0,0);
        if (m0 + lr < MM) av = *(const float4*)(Pb + (size_t)(m0+lr)*MM + n0 + lc);
        if (k0 + bc < KK) bv = *(const float4*)(Vb + (size_t)(n0+br)*KK + k0 + bc);
        __syncthreads();
        As[lc+0][lr]=av.x; As[lc+1][lr]=av.y; As[lc+2][lr]=av.z; As[lc+3][lr]=av.w;
        *(float4*)&Bs[br][bc] = bv;
        __syncthreads();
        #pragma unroll
        for (int nn = 0; nn < 16; nn++) {
            float4 a = *(const float4*)&As[nn][tm << 2];
            float4 bq = *(const float4*)&Bs[nn][tn << 2];
            acc[0][0]+=a.x*bq.x; acc[0][1]+=a.x*bq.y; acc[0][2]+=a.x*bq.z; acc[0][3]+=a.x*bq.w;
            acc[1][0]+=a.y*bq.x; acc[1][1]+=a.y*bq.y; acc[1][2]+=a.y*bq.z; acc[1][3]+=a.y*bq.w;
            acc[2][0]+=a.z*bq.x; acc[2][1]+=a.z*bq.y; acc[2][2]+=a.z*bq.z; acc[2][3]+=a.z*bq.w;
            acc[3][0]+=a.w*bq.x; acc[3][1]+=a.w*bq.y; acc[3][2]+=a.w*bq.z; acc[3][3]+=a.w*bq.w;
        }
    }
    #pragma unroll
    for (int i = 0; i < 4; i++) {
        int m = m0 + (tm<<2) + i; if (m >= MM) continue;
        #pragma unroll
        for (int j = 0; j < 4; j++) {
            int k = k0 + (tn<<2) + j; if (k >= KK) continue;
            O[((size_t)b*MM + m)*KK + k] = acc[i][j];
        }
    }
}

// ---------------- 6) unfold + residual -> ct[token][d] ----------------
__global__ void k_combine() {
    int i = blockIdx.x * 256 + threadIdx.x;    // over NPOS*D
    int dc = i & 127;
    int T  = i >> 7;
    int ww = T & 31, hh = (T >> 5) & 31;
    int bn = T >> 10;          // b*25 + n
    int b = bn / 25, n = bn % 25;
    int uu = n / 5, vv = n % 5;
    float r = g_kv[((size_t)b*D_ + dc)*S_ + n*(H_*W_) + hh*W_ + ww];
    float o;
    if (dc < 32) {
        int m = dc*32 + hh, k = n*32 + ww;          // permuted sf k-layout
        o = g_sfO[((size_t)b*M_SF + m)*K_SF + k];
    } else if (dc < 64) {
        int m = (dc-32)*5 + uu, k = (hh*5 + vv)*32 + ww;
        o = g_afO[((size_t)b*M_AF + m)*K_AF + k];
    } else {
        int m = hh*5 + uu, k = ((dc-64)*5 + vv)*32 + ww;
        o = g_saO[((size_t)b*M_SA + m)*K_SA + k];
    }
    g_ct[i] = o + r;
}

// ---------------- 7) LayerNorm (warp per token) ----------------
__global__ void k_ln(const float* __restrict__ gamma, const float* __restrict__ beta) {
    int T = blockIdx.x * 8 + (threadIdx.x >> 5);
    int lane = threadIdx.x & 31;
    const float* row = g_ct + (size_t)T * D_;
    float4 v = *(const float4*)(row + lane*4);
    float s = v.x + v.y + v.z + v.w;
    #pragma unroll
    for (int o = 16; o > 0; o >>= 1) s += __shfl_xor_sync(0xffffffffu, s, o);
    float mu = s * (1.f / 128.f);
    float cx = v.x - mu, cy = v.y - mu, cz = v.z - mu, cw = v.w - mu;
    float sq = cx*cx + cy*cy + cz*cz + cw*cw;
    #pragma unroll
    for (int o = 16; o > 0; o >>= 1) sq += __shfl_xor_sync(0xffffffffu, sq, o);
    float inv = rsqrtf(sq * (1.f / 128.f) + 1e-5f);
    float4 gmv = *(const float4*)(gamma + lane*4);
    float4 bev = *(const float4*)(beta + lane*4);
    float4 o4;
    o4.x = cx*inv*gmv.x + bev.x;
    o4.y = cy*inv*gmv.y + bev.y;
    o4.z = cz*inv*gmv.z + bev.z;
    o4.w = cw*inv*gmv.w + bev.w;
    *(float4*)(g_ln + (size_t)T*D_ + lane*4) = o4;
}

// ===================================================================
// 8) MLP gemms over [NPOS x 128]: 128-row tiles, 8x8 micro
// MODE 0: h1 = relu(ln @ W_m1)  MODE 1: ln <- h1 @ W_m2
// MODE 2: out = (ln+ct) @ W_out (N=64, scatter epilogue)
// ===================================================================
template<int MODE>
__global__ __launch_bounds__(256) void k_mlp_big(const float* __restrict__ Wm,
                                                 float* __restrict__ outp) {
    constexpr int NOUT = (MODE == 2) ? 64 : 128;
    const float* A = (MODE == 1) ? g_h1 : g_ln;
    int m0 = blockIdx.x * 128;
    __shared__ __align__(16) float As[8][132];
    __shared__ __align__(16) float Bs[8][132];
    int t = threadIdx.x, tx = t & 15, ty = t >> 4;
    int lrow = t >> 1, lcol = (t & 1) * 4;
    int vrow = t >> 5, vcol = (t & 31) * 4;
    float acc[8][8] = {};
    for (int k0 = 0; k0 < 128; k0 += 8) {
        float4 av = *(const float4*)(A + (size_t)(m0+lrow)*D_ + k0 + lcol);
        if (MODE == 2) {
            float4 a2 = *(const float4*)(g_ct + (size_t)(m0+lrow)*D_ + k0 + lcol);
            av.x += a2.x; av.y += a2.y; av.z += a2.z; av.w += a2.w;
        }
        float4 bv = make_float4(0,0,0,0);
        if (vcol < NOUT) bv = *(const float4*)(Wm + (size_t)(k0+vrow)*NOUT + vcol);
        __syncthreads();
        As[lcol+0][lrow]=av.x; As[lcol+1][lrow]=av.y; As[lcol+2][lrow]=av.z; As[lcol+3][lrow]=av.w;
        *(float4*)&Bs[vrow][vcol] = bv;
        __syncthreads();
        #pragma unroll
        for (int kk = 0; kk < 8; kk++) {
            float ar[8], br[8];
            *(float4*)&ar[0] = *(const float4*)&As[kk][ty*4];
            *(float4*)&ar[4] = *(const float4*)&As[kk][ty*4+64];
            *(float4*)&br[0] = *(const float4*)&Bs[kk][tx*4];
            *(float4*)&br[4] = *(const float4*)&Bs[kk][tx*4+64];
            #pragma unroll
            for (int i = 0; i < 8; i++)
                #pragma unroll
                for (int j = 0; j < 8; j++) acc[i][j] += ar[i]*br[j];
        }
    }
    if (MODE == 2) {
        // cols only in [0,64): j<4 group
        #pragma unroll
        for (int j = 0; j < 4; j++) {
            int nn = tx*4 + j;
            int m = m0 + ty*4;           // rows m..m+3 contiguous (s-fast)
            int ww = m & 31, hh = (m >> 5) & 31;
            int bn = m >> 10; int b = bn / 25, na = bn % 25;
            float* ob = outp + ((size_t)b*C_ + nn)*S_ + na*(H_*W_) + hh*W_ + ww;
            *(float4*)ob = make_float4(acc[0][j], acc[1][j], acc[2][j], acc[3][j]);
            int m2 = m + 64;
            int ww2 = m2 & 31, hh2 = (m2 >> 5) & 31;
            int bn2 = m2 >> 10; int b2 = bn2 / 25, na2 = bn2 % 25;
            float* ob2 = outp + ((size_t)b2*C_ + nn)*S_ + na2*(H_*W_) + hh2*W_ + ww2;
            *(float4*)ob2 = make_float4(acc[4][j], acc[5][j], acc[6][j], acc[7][j]);
        }
    } else {
        float* dst = (MODE == 0) ? g_h1 : g_ln;
        #pragma unroll
        for (int i = 0; i < 8; i++) {
            int m = m0 + ty*4 + (i < 4 ? i : i + 60);
            float4 v0 = make_float4(acc[i][0],acc[i][1],acc[i][2],acc[i][3]);
            float4 v1 = make_float4(acc[i][4],acc[i][5],acc[i][6],acc[i][7]);
            if (MODE == 0) {
                v0.x=fmaxf(v0.x,0.f); v0.y=fmaxf(v0.y,0.f); v0.z=fmaxf(v0.z,0.f); v0.w=fmaxf(v0.w,0.f);
                v1.x=fmaxf(v1.x,0.f); v1.y=fmaxf(v1.y,0.f); v1.z=fmaxf(v1.z,0.f); v1.w=fmaxf(v1.w,0.f);
            }
            *(float4*)(dst + (size_t)m*D_ + tx*4)      = v0;
            *(float4*)(dst + (size_t)m*D_ + tx*4 + 64) = v1;
        }
    }
}

// ---------------- launch ----------------
extern "C" void kernel_launch(void* const* d_in, const int* in_sizes, int n_in,
                              void* d_out, int out_size) {
    const float* x_lf = (const float*)d_in[0];
    const float* x_hf = (const float*)d_in[1];
    const float* W_in = (const float*)d_in[2];
    const float* W_kv = (const float*)d_in[3];
    const float* ln_g = (const float*)d_in[4];
    const float* ln_b = (const float*)d_in[5];
    const float* W_m1 = (const float*)d_in[6];
    const float* W_m2 = (const float*)d_in[7];
    const float* W_ot = (const float*)d_in[8];
    float* out = (float*)d_out;

    k_tokens_big<0><<<NPOS_/128, 256>>>(x_hf, W_in);
    k_tokens_big<1><<<NPOS_/128, 256>>>(x_lf, W_kv);

    // sf attention (big-tile path)
    k_fold<0><<<dim3(B_*M_SF, 2), 256>>>();
    k_score_sf<<<dim3(M_SF/128, M_SF/128, B_), 256>>>();
    k_softmax<0><<<B_*M_SF, 256>>>();
    k_pv_sf<<<dim3((K_SF+127)/128, M_SF/128, B_), 256>>>();

    // af attention
    k_fold<1><<<dim3(B_*M_AF, 2), 256>>>();
    k_score<1><<<dim3((M_AF+63)/64, (M_AF+63)/64, B_), 256>>>();
    k_softmax<1><<<B_*M_AF, 256>>>();
    k_pv<1><<<dim3(K_AF/64, (M_AF+63)/64, B_), 256>>>();

    // sa attention
    k_fold<2><<<dim3((M_SA+63)/64 ? B_*M_SA : B_*M_SA, 2), 256>>>();
    k_score<2><<<dim3((M_SA+63)/64, (M_SA+63)/64, B_), 256>>>();
    k_softmax<2><<<B_*M_SA, 256>>>();
    k_pv<2><<<dim3(K_SA/64, (M_SA+63)/64, B_), 256>>>();

    // combine + LN + MLP + out
    k_combine<<<(NPOS_*D_)/256, 256>>>();
    k_ln<<<NPOS_/8, 256>>>(ln_g, ln_b);
    k_mlp_big<0><<<NPOS_/128, 256>>>(W_m1, nullptr);
    k_mlp_big<1><<<NPOS_/128, 256>>>(W_m2, nullptr);
    k_mlp_big<2><<<NPOS_/128, 256>>>(W_ot, out);
}

// round 5
// speedup vs baseline: 1.9331x; 1.6800x over previous
#include <cuda_runtime.h>

// ---------------- problem constants ----------------
#define B_    4
#define C_    64
#define NA_   25
#define D_    128
#define H_    32
#define W_    32
#define S_    25600      // NA*H*W
#define NPOS_ 102400     // B*S
#define M_SF  1024
#define K_SF  800
#define M_AF  160
#define K_AF  5120
#define M_SA  160
#define K_SA  10240
// small-attention split-K partials live at g_att[0..), finals at g_att[FOFF_..)
#define FOFF_ (16*B_*M_AF*M_AF)   // 1,638,400 floats

// ---------------- scratch (device globals; no allocation) ----------------
__device__ float g_q [B_*D_*S_];
__device__ float g_kv[B_*D_*S_];

__device__ float g_sfQ[B_*M_SF*K_SF];
__device__ float g_sfK[B_*M_SF*K_SF];
__device__ float g_sfO[B_*M_SF*K_SF];
__device__ float g_afQ[B_*M_AF*K_AF];
__device__ float g_afK[B_*M_AF*K_AF];
__device__ float g_afO[B_*M_AF*K_AF];
__device__ float g_saQ[B_*M_SA*K_SA];
__device__ float g_saK[B_*M_SA*K_SA];
__device__ float g_saO[B_*M_SA*K_SA];

__device__ float g_ivq_sf[B_*M_SF];
__device__ float g_ivk_sf[B_*M_SF];
__device__ float g_ivq_af[B_*M_AF];
__device__ float g_ivk_af[B_*M_AF];
__device__ float g_ivq_sa[B_*M_SA];
__device__ float g_ivk_sa[B_*M_SA];

__device__ float g_att[B_*M_SF*M_SF];   // sf scores / af-sa partials+finals (sequential reuse)

__device__ float g_ct[NPOS_*D_];
__device__ float g_ln[NPOS_*D_];        // LN output; later reused as h2
__device__ float g_h1[NPOS_*D_];

// ===================================================================
// 1) token projection as 128x128x64 GEMM
// ===================================================================
template<int WHICH>
__global__ __launch_bounds__(256) void k_tokens_big(const float* __restrict__ x,
                                                    const float* __restrict__ Wm) {
    float* y = (WHICH == 0) ? g_q : g_kv;
    int m0 = blockIdx.x * 128;
    int b  = m0 / S_;
    int s0 = m0 % S_;
    const float* xb = x + (size_t)b*C_*S_;
    __shared__ __align__(16) float As[8][132];
    __shared__ __align__(16) float Bs[8][132];
    int t = threadIdx.x, tx = t & 15, ty = t >> 4;
    int crow = t >> 5, ccol = (t & 31) * 4;
    float acc[8][8] = {};
    for (int k0 = 0; k0 < C_; k0 += 8) {
        float4 av = *(const float4*)(xb + (size_t)(k0+crow)*S_ + s0 + ccol);
        float4 bv = *(const float4*)(Wm + (size_t)(k0+crow)*D_ + ccol);
        __syncthreads();
        *(float4*)&As[crow][ccol] = av;
        *(float4*)&Bs[crow][ccol] = bv;
        __syncthreads();
        #pragma unroll
        for (int kk = 0; kk < 8; kk++) {
            float ar[8], br[8];
            *(float4*)&ar[0] = *(const float4*)&As[kk][ty*4];
            *(float4*)&ar[4] = *(const float4*)&As[kk][ty*4+64];
            *(float4*)&br[0] = *(const float4*)&Bs[kk][tx*4];
            *(float4*)&br[4] = *(const float4*)&Bs[kk][tx*4+64];
            #pragma unroll
            for (int i = 0; i < 8; i++)
                #pragma unroll
                for (int j = 0; j < 8; j++) acc[i][j] += ar[i]*br[j];
        }
    }
    #pragma unroll
    for (int j = 0; j < 8; j++) {
        int dc = tx*4 + (j < 4 ? j : j + 60);
        float* yb = y + ((size_t)b*D_ + dc)*S_ + s0;
        *(float4*)(yb + ty*4)      = make_float4(acc[0][j], acc[1][j], acc[2][j], acc[3][j]);
        *(float4*)(yb + 64 + ty*4) = make_float4(acc[4][j], acc[5][j], acc[6][j], acc[7][j]);
    }
}

// ---------------- 2) fold gather + inverse L2 norms ----------------
template<int TYPE>
__global__ void k_fold() {
    constexpr int MM  = TYPE==0 ? M_SF : (TYPE==1 ? M_AF : M_SA);
    constexpr int KK  = TYPE==0 ? K_SF : (TYPE==1 ? K_AF : K_SA);
    constexpr int OFF = TYPE==0 ? 0 : (TYPE==1 ? 32 : 64);
    int row = blockIdx.x;
    int isK = blockIdx.y;
    int b = row / MM, m = row % MM;
    const float* src = isK ? g_kv : g_q;
    float* dst; float* ivd;
    if (TYPE==0) { dst = isK ? g_sfK : g_sfQ; ivd = isK ? g_ivk_sf : g_ivq_sf; }
    else if (TYPE==1) { dst = isK ? g_afK : g_afQ; ivd = isK ? g_ivk_af : g_ivq_af; }
    else { dst = isK ? g_saK : g_saQ; ivd = isK ? g_ivk_sa : g_ivq_sa; }
    const float* base = src + ((size_t)b*D_ + OFF)*S_;
    float* drow = dst + (size_t)row*KK;
    int t = threadIdx.x;
    float ss = 0.f;
    if (TYPE == 0) {
        int ch = m >> 5, hh = m & 31;
        const float* bp = base + (size_t)ch*S_ + hh*W_;
        for (int kk = t; kk < KK; kk += 256) {
            int n = kk >> 5, ww = kk & 31;
            float v = bp[n*(H_*W_) + ww];
            drow[kk] = v;
            ss += v*v;
        }
    } else if (TYPE == 1) {
        int ch = m / 5, uu = m % 5;
        const float* bp = base + (size_t)ch*S_;
        for (int k = t; k < KK; k += 256) {
            int hh = k / 160, vv = (k >> 5) % 5, ww = k & 31;
            int n = uu*5 + vv;
            float v = bp[n*(H_*W_) + hh*W_ + ww];
            drow[k] = v;
            ss += v*v;
        }
    } else {
        int hh = m / 5, uu = m % 5;
        for (int k = t; k < KK; k += 256) {
            int ch = k / 160, vv = (k >> 5) % 5, ww = k & 31;
            int n = uu*5 + vv;
            float v = base[(size_t)ch*S_ + n*(H_*W_) + hh*W_ + ww];
            drow[k] = v;
            ss += v*v;
        }
    }
    __shared__ float red[256];
    red[t] = ss; __syncthreads();
    for (int st = 128; st > 0; st >>= 1) { if (t < st) red[t] += red[t + st]; __syncthreads(); }
    if (t == 0) ivd[row] = 1.f / fmaxf(sqrtf(red[0]), 1e-12f);
}

// ===================================================================
// 3a) SF raw scores: 128(m)x64(n) tiles, 8x4 micro. Raw dots only;
//     scale + mask applied in softmax. Masked tiles skipped entirely.
// ===================================================================
__global__ __launch_bounds__(256) void k_score_sf() {
    int b = blockIdx.z, m0 = blockIdx.y*128, n0 = blockIdx.x*64;
    if (n0 > m0 + 127) return;
    const float* Ab = g_sfQ + (size_t)b*M_SF*K_SF;
    const float* Bb = g_sfK + (size_t)b*M_SF*K_SF;
    __shared__ __align__(16) float As[8][132];
    __shared__ __align__(16) float Bs[8][68];
    int t = threadIdx.x, tx = t & 15, ty = t >> 4;
    int lra = t >> 1, lca = (t & 1) * 4;     // A: 128 rows x 8 cols
    int lrb = (t & 127) >> 1;                // B: 64 rows x 8 cols (t<128)
    float acc[8][4] = {};
    for (int k0 = 0; k0 < K_SF; k0 += 8) {
        float4 av = *(const float4*)(Ab + (size_t)(m0+lra)*K_SF + k0 + lca);
        float4 bv = make_float4(0,0,0,0);
        if (t < 128) bv = *(const float4*)(Bb + (size_t)(n0+lrb)*K_SF + k0 + lca);
        __syncthreads();
        As[lca+0][lra]=av.x; As[lca+1][lra]=av.y; As[lca+2][lra]=av.z; As[lca+3][lra]=av.w;
        if (t < 128) {
            Bs[lca+0][lrb]=bv.x; Bs[lca+1][lrb]=bv.y; Bs[lca+2][lrb]=bv.z; Bs[lca+3][lrb]=bv.w;
        }
        __syncthreads();
        #pragma unroll
        for (int kk = 0; kk < 8; kk++) {
            float ar[8], br[4];
            *(float4*)&ar[0] = *(const float4*)&As[kk][ty*4];
            *(float4*)&ar[4] = *(const float4*)&As[kk][ty*4+64];
            *(float4*)&br[0] = *(const float4*)&Bs[kk][tx*4];
            #pragma unroll
            for (int i = 0; i < 8; i++)
                #pragma unroll
                for (int j = 0; j < 4; j++) acc[i][j] += ar[i]*br[j];
        }
    }
    float* att = g_att + (size_t)b*M_SF*M_SF;
    #pragma unroll
    for (int i = 0; i < 8; i++) {
        int m = m0 + ty*4 + (i < 4 ? i : i + 60);
        *(float4*)(att + (size_t)m*M_SF + n0 + tx*4) =
            make_float4(acc[i][0], acc[i][1], acc[i][2], acc[i][3]);
    }
}

// ===================================================================
// 4a) SF softmax: scale + causal mask + softmax in one pass (regs only).
//     Writes probabilities for n<=m, exact zeros for m<n<tile boundary.
// ===================================================================
__global__ __launch_bounds__(256) void k_softmax_sf() {
    int blk = blockIdx.x;
    int b = blk >> 10, m = blk & 1023;
    float* p = g_att + ((size_t)b*M_SF + m)*M_SF;
    int LIMW = ((m >> 7) + 1) << 7;          // pv_sf reads up to here
    float qn = g_ivq_sf[b*M_SF + m];
    const float* ivk = g_ivk_sf + b*M_SF;
    int t = threadIdx.x;
    __shared__ float red[256];
    float vv[4];
    float mx = -3.4e38f;
    #pragma unroll
    for (int i = 0; i < 4; i++) {
        int k = t + i*256;
        if (k < LIMW) {
            float v = (k <= m) ? p[k]*qn*ivk[k] : -3.4e38f;
            vv[i] = v; mx = fmaxf(mx, v);
        }
    }
    red[t] = mx; __syncthreads();
    for (int st = 128; st > 0; st >>= 1) { if (t < st) red[t] = fmaxf(red[t], red[t+st]); __syncthreads(); }
    mx = red[0]; __syncthreads();
    float s = 0.f;
    #pragma unroll
    for (int i = 0; i < 4; i++) {
        int k = t + i*256;
        if (k < LIMW) {
            float e = (k <= m) ? expf(vv[i] - mx) : 0.f;
            vv[i] = e; s += e;
        }
    }
    red[t] = s; __syncthreads();
    for (int st = 128; st > 0; st >>= 1) { if (t < st) red[t] += red[t+st]; __syncthreads(); }
    float inv = 1.f / red[0];
    #pragma unroll
    for (int i = 0; i < 4; i++) {
        int k = t + i*256;
        if (k < LIMW) p[k] = vv[i]*inv;
    }
}

// ===================================================================
// 5a) SF O = P @ V : 128(m)x64(k) tiles, 8x4 micro, causal bound
// ===================================================================
__global__ __launch_bounds__(256) void k_pv_sf() {
    int b = blockIdx.z, m0 = blockIdx.y*128, k0 = blockIdx.x*64;
    const float* Pb = g_att + (size_t)b*M_SF*M_SF;
    const float* Vb = g_sfK + (size_t)b*M_SF*K_SF;
    __shared__ __align__(16) float As[8][132];
    __shared__ __align__(16) float Bs[8][68];
    int t = threadIdx.x, tx = t & 15, ty = t >> 4;
    int lra = t >> 1, lca = (t & 1) * 4;     // P: 128 x 8
    int vr = (t & 127) >> 4, vc = (t & 15) * 4;  // V: 8 x 64 (t<128)
    bool bval = (t < 128) && (k0 + vc < K_SF);
    float acc[8][4] = {};
    int NLIM = m0 + 128;
    for (int n0 = 0; n0 < NLIM; n0 += 8) {
        float4 av = *(const float4*)(Pb + (size_t)(m0+lra)*M_SF + n0 + lca);
        float4 bv = make_float4(0,0,0,0);
        if (bval) bv = *(const float4*)(Vb + (size_t)(n0+vr)*K_SF + k0 + vc);
        __syncthreads();
        As[lca+0][lra]=av.x; As[lca+1][lra]=av.y; As[lca+2][lra]=av.z; As[lca+3][lra]=av.w;
        if (t < 128) *(float4*)&Bs[vr][vc] = bv;
        __syncthreads();
        #pragma unroll
        for (int kk = 0; kk < 8; kk++) {
            float ar[8], br[4];
            *(float4*)&ar[0] = *(const float4*)&As[kk][ty*4];
            *(float4*)&ar[4] = *(const float4*)&As[kk][ty*4+64];
            *(float4*)&br[0] = *(const float4*)&Bs[kk][tx*4];
            #pragma unroll
            for (int i = 0; i < 8; i++)
                #pragma unroll
                for (int j = 0; j < 4; j++) acc[i][j] += ar[i]*br[j];
        }
    }
    float* O = g_sfO + (size_t)b*M_SF*K_SF;
    int c = k0 + tx*4;
    if (c < K_SF) {
        #pragma unroll
        for (int i = 0; i < 8; i++) {
            int m = m0 + ty*4 + (i < 4 ? i : i + 60);
            *(float4*)(O + (size_t)m*K_SF + c) =
                make_float4(acc[i][0], acc[i][1], acc[i][2], acc[i][3]);
        }
    }
}

// ===================================================================
// 3b) af/sa raw scores, split-K: each block does one 64x64 tile over one
//     K-chunk of 640, writing partials to g_att[ch][b][m][n].
// ===================================================================
template<int TYPE>   // 1=af (8 chunks), 2=sa (16 chunks)
__global__ __launch_bounds__(256) void k_score_small() {
    constexpr int MM = 160;
    constexpr int KK = TYPE==1 ? K_AF : K_SA;
    constexpr int CH = TYPE==1 ? 8 : 16;
    constexpr int CHK = KK / CH;             // 640
    const float* Qf = TYPE==1 ? g_afQ : g_saQ;
    const float* Kf = TYPE==1 ? g_afK : g_saK;
    int z = blockIdx.z;
    int b = z / CH, ch = z % CH;
    int m0 = blockIdx.y*64, n0 = blockIdx.x*64;
    if (n0 > m0 + 63) return;
    const float* Ab = Qf + (size_t)b*MM*KK;
    const float* Bb = Kf + (size_t)b*MM*KK;
    __shared__ __align__(16) float As[16][64];
    __shared__ __align__(16) float Bs[16][64];
    int t = threadIdx.x, tn = t & 15, tm = t >> 4;
    int lr = t >> 2, lc = (t & 3) << 2;
    float acc[4][4] = {};
    int kbeg = ch*CHK, kend = kbeg + CHK;
    for (int k0 = kbeg; k0 < kend; k0 += 16) {
        float4 av = make_float4(0,0,0,0), bv = make_float4(0,0,0,0);
        if (m0 + lr < MM) av = *(const float4*)(Ab + (size_t)(m0+lr)*KK + k0 + lc);
        if (n0 + lr < MM) bv = *(const float4*)(Bb + (size_t)(n0+lr)*KK + k0 + lc);
        __syncthreads();
        As[lc+0][lr]=av.x; As[lc+1][lr]=av.y; As[lc+2][lr]=av.z; As[lc+3][lr]=av.w;
        Bs[lc+0][lr]=bv.x; Bs[lc+1][lr]=bv.y; Bs[lc+2][lr]=bv.z; Bs[lc+3][lr]=bv.w;
        __syncthreads();
        #pragma unroll
        for (int kk = 0; kk < 16; kk++) {
            float4 a = *(const float4*)&As[kk][tm << 2];
            float4 bq = *(const float4*)&Bs[kk][tn << 2];
            acc[0][0]+=a.x*bq.x; acc[0][1]+=a.x*bq.y; acc[0][2]+=a.x*bq.z; acc[0][3]+=a.x*bq.w;
            acc[1][0]+=a.y*bq.x; acc[1][1]+=a.y*bq.y; acc[1][2]+=a.y*bq.z; acc[1][3]+=a.y*bq.w;
            acc[2][0]+=a.z*bq.x; acc[2][1]+=a.z*bq.y; acc[2][2]+=a.z*bq.z; acc[2][3]+=a.z*bq.w;
            acc[3][0]+=a.w*bq.x; acc[3][1]+=a.w*bq.y; acc[3][2]+=a.w*bq.z; acc[3][3]+=a.w*bq.w;
        }
    }
    float* part = g_att + ((size_t)(ch*B_ + b)*MM)*MM;
    #pragma unroll
    for (int i = 0; i < 4; i++) {
        int m = m0 + (tm<<2) + i; if (m >= MM) continue;
        #pragma unroll
        for (int j = 0; j < 4; j++) {
            int n = n0 + (tn<<2) + j; if (n >= MM) continue;
            part[(size_t)m*MM + n] = acc[i][j];
        }
    }
}

// ===================================================================
// 4b) af/sa softmax: sum split-K partials + scale + mask + softmax.
//     Writes finals (zeros beyond diagonal) to g_att + FOFF_.
// ===================================================================
template<int TYPE>
__global__ __launch_bounds__(256) void k_softmax_small() {
    constexpr int MM = 160;
    constexpr int CH = TYPE==1 ? 8 : 16;
    const float* ivq = TYPE==1 ? g_ivq_af : g_ivq_sa;
    const float* ivk = TYPE==1 ? g_ivk_af : g_ivk_sa;
    int blk = blockIdx.x;
    int b = blk / MM, m = blk % MM;
    int t = threadIdx.x;
    float v = -3.4e38f;
    if (t < MM && t <= m) {
        float s = 0.f;
        #pragma unroll 4
        for (int ch = 0; ch < CH; ch++)
            s += g_att[(((size_t)(ch*B_ + b))*MM + m)*MM + t];
        v = s * ivq[b*MM + m] * ivk[b*MM + t];
    }
    __shared__ float red[256];
    red[t] = v; __syncthreads();
    for (int st = 128; st > 0; st >>= 1) { if (t < st) red[t] = fmaxf(red[t], red[t+st]); __syncthreads(); }
    float mx = red[0]; __syncthreads();
    float e = (t < MM && t <= m) ? expf(v - mx) : 0.f;
    red[t] = e; __syncthreads();
    for (int st = 128; st > 0; st >>= 1) { if (t < st) red[t] += red[t+st]; __syncthreads(); }
    float inv = 1.f / red[0];
    if (t < MM) g_att[FOFF_ + ((size_t)b*MM + m)*MM + t] = e*inv;
}

// ---------------- 5b) af/sa O = P @ V (reads finals; causal bound) ----------------
template<int TYPE>
__global__ __launch_bounds__(256) void k_pv() {
    constexpr int MM = 160;
    constexpr int KK = TYPE==1 ? K_AF : K_SA;
    const float* V = TYPE==1 ? g_afK : g_saK;
    float* O = TYPE==1 ? g_afO : g_saO;
    int b = blockIdx.z, m0 = blockIdx.y*64, k0 = blockIdx.x*64;
    int t = threadIdx.x, tn = t & 15, tm = t >> 4;
    const float* Pb = g_att + FOFF_ + (size_t)b*MM*MM;
    const float* Vb = V + (size_t)b*MM*KK;
    __shared__ __align__(16) float As[16][64];
    __shared__ __align__(16) float Bs[16][64];
    int lr = t >> 2, lc = (t & 3) << 2;
    int br = t >> 4, bc = (t & 15) << 2;
    float acc[4][4] = {};
    int NLIM = (m0 + 64 < MM) ? m0 + 64 : MM;    // P rows are 0 beyond own tile
    for (int n0 = 0; n0 < NLIM; n0 += 16) {
        float4 av = make_float4(0,0,0,0), bv = make_float4(0,0,0,0);
        if (m0 + lr < MM) av = *(const float4*)(Pb + (size_t)(m0+lr)*MM + n0 + lc);
        if (n0 + br < MM) bv = *(const float4*)(Vb + (size_t)(n0+br)*KK + k0 + bc);
        __syncthreads();
        As[lc+0][lr]=av.x; As[lc+1][lr]=av.y; As[lc+2][lr]=av.z; As[lc+3][lr]=av.w;
        *(float4*)&Bs[br][bc] = bv;
        __syncthreads();
        #pragma unroll
        for (int nn = 0; nn < 16; nn++) {
            float4 a = *(const float4*)&As[nn][tm << 2];
            float4 bq = *(const float4*)&Bs[nn][tn << 2];
            acc[0][0]+=a.x*bq.x; acc[0][1]+=a.x*bq.y; acc[0][2]+=a.x*bq.z; acc[0][3]+=a.x*bq.w;
            acc[1][0]+=a.y*bq.x; acc[1][1]+=a.y*bq.y; acc[1][2]+=a.y*bq.z; acc[1][3]+=a.y*bq.w;
            acc[2][0]+=a.z*bq.x; acc[2][1]+=a.z*bq.y; acc[2][2]+=a.z*bq.z; acc[2][3]+=a.z*bq.w;
            acc[3][0]+=a.w*bq.x; acc[3][1]+=a.w*bq.y; acc[3][2]+=a.w*bq.z; acc[3][3]+=a.w*bq.w;
        }
    }
    #pragma unroll
    for (int i = 0; i < 4; i++) {
        int m = m0 + (tm<<2) + i; if (m >= MM) continue;
        #pragma unroll
        for (int j = 0; j < 4; j++) {
            int k = k0 + (tn<<2) + j;
            O[((size_t)b*MM + m)*KK + k] = acc[i][j];
        }
    }
}

// ---------------- 6) unfold + residual -> ct[token][d] ----------------
__global__ void k_combine() {
    int i = blockIdx.x * 256 + threadIdx.x;
    int dc = i & 127;
    int T  = i >> 7;
    int ww = T & 31, hh = (T >> 5) & 31;
    int bn = T >> 10;
    int b = bn / 25, n = bn % 25;
    int uu = n / 5, vv = n % 5;
    float r = g_kv[((size_t)b*D_ + dc)*S_ + n*(H_*W_) + hh*W_ + ww];
    float o;
    if (dc < 32) {
        int m = dc*32 + hh, k = n*32 + ww;
        o = g_sfO[((size_t)b*M_SF + m)*K_SF + k];
    } else if (dc < 64) {
        int m = (dc-32)*5 + uu, k = (hh*5 + vv)*32 + ww;
        o = g_afO[((size_t)b*M_AF + m)*K_AF + k];
    } else {
        int m = hh*5 + uu, k = ((dc-64)*5 + vv)*32 + ww;
        o = g_saO[((size_t)b*M_SA + m)*K_SA + k];
    }
    g_ct[i] = o + r;
}

// ---------------- 7) LayerNorm (warp per token) ----------------
__global__ void k_ln(const float* __restrict__ gamma, const float* __restrict__ beta) {
    int T = blockIdx.x * 8 + (threadIdx.x >> 5);
    int lane = threadIdx.x & 31;
    const float* row = g_ct + (size_t)T * D_;
    float4 v = *(const float4*)(row + lane*4);
    float s = v.x + v.y + v.z + v.w;
    #pragma unroll
    for (int o = 16; o > 0; o >>= 1) s += __shfl_xor_sync(0xffffffffu, s, o);
    float mu = s * (1.f / 128.f);
    float cx = v.x - mu, cy = v.y - mu, cz = v.z - mu, cw = v.w - mu;
    float sq = cx*cx + cy*cy + cz*cz + cw*cw;
    #pragma unroll
    for (int o = 16; o > 0; o >>= 1) sq += __shfl_xor_sync(0xffffffffu, sq, o);
    float inv = rsqrtf(sq * (1.f / 128.f) + 1e-5f);
    float4 gmv = *(const float4*)(gamma + lane*4);
    float4 bev = *(const float4*)(beta + lane*4);
    float4 o4;
    o4.x = cx*inv*gmv.x + bev.x;
    o4.y = cy*inv*gmv.y + bev.y;
    o4.z = cz*inv*gmv.z + bev.z;
    o4.w = cw*inv*gmv.w + bev.w;
    *(float4*)(g_ln + (size_t)T*D_ + lane*4) = o4;
}

// ===================================================================
// 8) MLP gemms: 128-row tiles, 8x8 micro
// ===================================================================
template<int MODE>
__global__ __launch_bounds__(256) void k_mlp_big(const float* __restrict__ Wm,
                                                 float* __restrict__ outp) {
    constexpr int NOUT = (MODE == 2) ? 64 : 128;
    const float* A = (MODE == 1) ? g_h1 : g_ln;
    int m0 = blockIdx.x * 128;
    __shared__ __align__(16) float As[8][132];
    __shared__ __align__(16) float Bs[8][132];
    int t = threadIdx.x, tx = t & 15, ty = t >> 4;
    int lrow = t >> 1, lcol = (t & 1) * 4;
    int vrow = t >> 5, vcol = (t & 31) * 4;
    float acc[8][8] = {};
    for (int k0 = 0; k0 < 128; k0 += 8) {
        float4 av = *(const float4*)(A + (size_t)(m0+lrow)*D_ + k0 + lcol);
        if (MODE == 2) {
            float4 a2 = *(const float4*)(g_ct + (size_t)(m0+lrow)*D_ + k0 + lcol);
            av.x += a2.x; av.y += a2.y; av.z += a2.z; av.w += a2.w;
        }
        float4 bv = make_float4(0,0,0,0);
        if (vcol < NOUT) bv = *(const float4*)(Wm + (size_t)(k0+vrow)*NOUT + vcol);
        __syncthreads();
        As[lcol+0][lrow]=av.x; As[lcol+1][lrow]=av.y; As[lcol+2][lrow]=av.z; As[lcol+3][lrow]=av.w;
        *(float4*)&Bs[vrow][vcol] = bv;
        __syncthreads();
        #pragma unroll
        for (int kk = 0; kk < 8; kk++) {
            float ar[8], br[8];
            *(float4*)&ar[0] = *(const float4*)&As[kk][ty*4];
            *(float4*)&ar[4] = *(const float4*)&As[kk][ty*4+64];
            *(float4*)&br[0] = *(const float4*)&Bs[kk][tx*4];
            *(float4*)&br[4] = *(const float4*)&Bs[kk][tx*4+64];
            #pragma unroll
            for (int i = 0; i < 8; i++)
                #pragma unroll
                for (int j = 0; j < 8; j++) acc[i][j] += ar[i]*br[j];
        }
    }
    if (MODE == 2) {
        #pragma unroll
        for (int j = 0; j < 4; j++) {
            int nn = tx*4 + j;
            int m = m0 + ty*4;
            int ww = m & 31, hh = (m >> 5) & 31;
            int bn = m >> 10; int b = bn / 25, na = bn % 25;
            float* ob = outp + ((size_t)b*C_ + nn)*S_ + na*(H_*W_) + hh*W_ + ww;
            *(float4*)ob = make_float4(acc[0][j], acc[1][j], acc[2][j], acc[3][j]);
            int m2 = m + 64;
            int ww2 = m2 & 31, hh2 = (m2 >> 5) & 31;
            int bn2 = m2 >> 10; int b2 = bn2 / 25, na2 = bn2 % 25;
            float* ob2 = outp + ((size_t)b2*C_ + nn)*S_ + na2*(H_*W_) + hh2*W_ + ww2;
            *(float4*)ob2 = make_float4(acc[4][j], acc[5][j], acc[6][j], acc[7][j]);
        }
    } else {
        float* dst = (MODE == 0) ? g_h1 : g_ln;
        #pragma unroll
        for (int i = 0; i < 8; i++) {
            int m = m0 + ty*4 + (i < 4 ? i : i + 60);
            float4 v0 = make_float4(acc[i][0],acc[i][1],acc[i][2],acc[i][3]);
            float4 v1 = make_float4(acc[i][4],acc[i][5],acc[i][6],acc[i][7]);
            if (MODE == 0) {
                v0.x=fmaxf(v0.x,0.f); v0.y=fmaxf(v0.y,0.f); v0.z=fmaxf(v0.z,0.f); v0.w=fmaxf(v0.w,0.f);
                v1.x=fmaxf(v1.x,0.f); v1.y=fmaxf(v1.y,0.f); v1.z=fmaxf(v1.z,0.f); v1.w=fmaxf(v1.w,0.f);
            }
            *(float4*)(dst + (size_t)m*D_ + tx*4)      = v0;
            *(float4*)(dst + (size_t)m*D_ + tx*4 + 64) = v1;
        }
    }
}

// ---------------- launch ----------------
extern "C" void kernel_launch(void* const* d_in, const int* in_sizes, int n_in,
                              void* d_out, int out_size) {
    const float* x_lf = (const float*)d_in[0];
    const float* x_hf = (const float*)d_in[1];
    const float* W_in = (const float*)d_in[2];
    const float* W_kv = (const float*)d_in[3];
    const float* ln_g = (const float*)d_in[4];
    const float* ln_b = (const float*)d_in[5];
    const float* W_m1 = (const float*)d_in[6];
    const float* W_m2 = (const float*)d_in[7];
    const float* W_ot = (const float*)d_in[8];
    float* out = (float*)d_out;

    k_tokens_big<0><<<NPOS_/128, 256>>>(x_hf, W_in);
    k_tokens_big<1><<<NPOS_/128, 256>>>(x_lf, W_kv);

    // sf attention
    k_fold<0><<<dim3(B_*M_SF, 2), 256>>>();
    k_score_sf<<<dim3(M_SF/64, M_SF/128, B_), 256>>>();
    k_softmax_sf<<<B_*M_SF, 256>>>();
    k_pv_sf<<<dim3((K_SF+63)/64, M_SF/128, B_), 256>>>();

    // af attention (split-K 8)
    k_fold<1><<<dim3(B_*M_AF, 2), 256>>>();
    k_score_small<1><<<dim3(3, 3, B_*8), 256>>>();
    k_softmax_small<1><<<B_*M_AF, 256>>>();
    k_pv<1><<<dim3(K_AF/64, 3, B_), 256>>>();

    // sa attention (split-K 16)
    k_fold<2><<<dim3(B_*M_SA, 2), 256>>>();
    k_score_small<2><<<dim3(3, 3, B_*16), 256>>>();
    k_softmax_small<2><<<B_*M_SA, 256>>>();
    k_pv<2><<<dim3(K_SA/64, 3, B_), 256>>>();

    // combine + LN + MLP + out
    k_combine<<<(NPOS_*D_)/256, 256>>>();
    k_ln<<<NPOS_/8, 256>>>(ln_g, ln_b);
    k_mlp_big<0><<<NPOS_/128, 256>>>(W_m1, nullptr);
    k_mlp_big<1><<<NPOS_/128, 256>>>(W_m2, nullptr);
    k_mlp_big<2><<<NPOS_/128, 256>>>(W_ot, out);
}

// round 6
// speedup vs baseline: 2.0127x; 1.0412x over previous
#include <cuda_runtime.h>

// ---------------- problem constants ----------------
#define B_    4
#define C_    64
#define NA_   25
#define D_    128
#define H_    32
#define W_    32
#define S_    25600      // NA*H*W
#define NPOS_ 102400     // B*S
#define M_SF  1024
#define K_SF  800
#define M_AF  160
#define K_AF  5120
#define M_SA  160
#define K_SA  10240
#define FOFF_ (16*B_*M_AF*M_AF)

// ---------------- scratch (device globals; no allocation) ----------------
__device__ float g_q [B_*D_*S_];
__device__ float g_kv[B_*D_*S_];

__device__ float g_sfQ[B_*M_SF*K_SF];
__device__ float g_sfK[B_*M_SF*K_SF];
__device__ float g_sfO[B_*M_SF*K_SF];
__device__ float g_afQ[B_*M_AF*K_AF];
__device__ float g_afK[B_*M_AF*K_AF];
__device__ float g_afO[B_*M_AF*K_AF];
__device__ float g_saQ[B_*M_SA*K_SA];
__device__ float g_saK[B_*M_SA*K_SA];
__device__ float g_saO[B_*M_SA*K_SA];

__device__ float g_ivq_sf[B_*M_SF];
__device__ float g_ivk_sf[B_*M_SF];
__device__ float g_ivq_af[B_*M_AF];
__device__ float g_ivk_af[B_*M_AF];
__device__ float g_ivq_sa[B_*M_SA];
__device__ float g_ivk_sa[B_*M_SA];

__device__ float g_att[B_*M_SF*M_SF];

__device__ float g_ct[NPOS_*D_];
__device__ float g_ln[NPOS_*D_];
__device__ float g_h1[NPOS_*D_];

#define MICRO88(As_, Bs_) \
    _Pragma("unroll") \
    for (int kk = 0; kk < 8; kk++) { \
        float ar[8], br[8]; \
        *(float4*)&ar[0] = *(const float4*)&As_[kk][ty*4]; \
        *(float4*)&ar[4] = *(const float4*)&As_[kk][ty*4+64]; \
        *(float4*)&br[0] = *(const float4*)&Bs_[kk][tx*4]; \
        *(float4*)&br[4] = *(const float4*)&Bs_[kk][tx*4+64]; \
        _Pragma("unroll") \
        for (int i = 0; i < 8; i++) \
            _Pragma("unroll") \
            for (int j = 0; j < 8; j++) acc[i][j] += ar[i]*br[j]; \
    }

#define MICRO84(As_, Bs_) \
    _Pragma("unroll") \
    for (int kk = 0; kk < 8; kk++) { \
        float ar[8], br[4]; \
        *(float4*)&ar[0] = *(const float4*)&As_[kk][ty*4]; \
        *(float4*)&ar[4] = *(const float4*)&As_[kk][ty*4+64]; \
        *(float4*)&br[0] = *(const float4*)&Bs_[kk][tx*4]; \
        _Pragma("unroll") \
        for (int i = 0; i < 8; i++) \
            _Pragma("unroll") \
            for (int j = 0; j < 4; j++) acc[i][j] += ar[i]*br[j]; \
    }

// ===================================================================
// 1) token projection: 128x128x64 GEMM, double-buffered
// ===================================================================
template<int WHICH>
__global__ __launch_bounds__(256) void k_tokens_big(const float* __restrict__ x,
                                                    const float* __restrict__ Wm) {
    float* y = (WHICH == 0) ? g_q : g_kv;
    int m0 = blockIdx.x * 128;
    int b  = m0 / S_;
    int s0 = m0 % S_;
    const float* xb = x + (size_t)b*C_*S_;
    __shared__ __align__(16) float As[2][8][132];
    __shared__ __align__(16) float Bs[2][8][132];
    int t = threadIdx.x, tx = t & 15, ty = t >> 4;
    int crow = t >> 5, ccol = (t & 31) * 4;
    float acc[8][8] = {};
    float4 av = *(const float4*)(xb + (size_t)crow*S_ + s0 + ccol);
    float4 bv = *(const float4*)(Wm + (size_t)crow*D_ + ccol);
    *(float4*)&As[0][crow][ccol] = av;
    *(float4*)&Bs[0][crow][ccol] = bv;
    __syncthreads();
    const int nit = C_/8;
    for (int it = 0; it < nit; it++) {
        int cur = it & 1;
        if (it + 1 < nit) {
            int k0 = (it+1)*8;
            av = *(const float4*)(xb + (size_t)(k0+crow)*S_ + s0 + ccol);
            bv = *(const float4*)(Wm + (size_t)(k0+crow)*D_ + ccol);
        }
        MICRO88(As[cur], Bs[cur]);
        if (it + 1 < nit) {
            *(float4*)&As[cur^1][crow][ccol] = av;
            *(float4*)&Bs[cur^1][crow][ccol] = bv;
            __syncthreads();
        }
    }
    #pragma unroll
    for (int j = 0; j < 8; j++) {
        int dc = tx*4 + (j < 4 ? j : j + 60);
        float* yb = y + ((size_t)b*D_ + dc)*S_ + s0;
        *(float4*)(yb + ty*4)      = make_float4(acc[0][j], acc[1][j], acc[2][j], acc[3][j]);
        *(float4*)(yb + 64 + ty*4) = make_float4(acc[4][j], acc[5][j], acc[6][j], acc[7][j]);
    }
}

// ---------------- 2) fold gather + inverse L2 norms ----------------
template<int TYPE>
__global__ void k_fold() {
    constexpr int MM  = TYPE==0 ? M_SF : (TYPE==1 ? M_AF : M_SA);
    constexpr int KK  = TYPE==0 ? K_SF : (TYPE==1 ? K_AF : K_SA);
    constexpr int OFF = TYPE==0 ? 0 : (TYPE==1 ? 32 : 64);
    int row = blockIdx.x;
    int isK = blockIdx.y;
    int b = row / MM, m = row % MM;
    const float* src = isK ? g_kv : g_q;
    float* dst; float* ivd;
    if (TYPE==0) { dst = isK ? g_sfK : g_sfQ; ivd = isK ? g_ivk_sf : g_ivq_sf; }
    else if (TYPE==1) { dst = isK ? g_afK : g_afQ; ivd = isK ? g_ivk_af : g_ivq_af; }
    else { dst = isK ? g_saK : g_saQ; ivd = isK ? g_ivk_sa : g_ivq_sa; }
    const float* base = src + ((size_t)b*D_ + OFF)*S_;
    float* drow = dst + (size_t)row*KK;
    int t = threadIdx.x;
    float ss = 0.f;
    if (TYPE == 0) {
        int ch = m >> 5, hh = m & 31;
        const float* bp = base + (size_t)ch*S_ + hh*W_;
        for (int kk = t; kk < KK; kk += 256) {
            int n = kk >> 5, ww = kk & 31;
            float v = bp[n*(H_*W_) + ww];
            drow[kk] = v;
            ss += v*v;
        }
    } else if (TYPE == 1) {
        int ch = m / 5, uu = m % 5;
        const float* bp = base + (size_t)ch*S_;
        for (int k = t; k < KK; k += 256) {
            int hh = k / 160, vv = (k >> 5) % 5, ww = k & 31;
            int n = uu*5 + vv;
            float v = bp[n*(H_*W_) + hh*W_ + ww];
            drow[k] = v;
            ss += v*v;
        }
    } else {
        int hh = m / 5, uu = m % 5;
        for (int k = t; k < KK; k += 256) {
            int ch = k / 160, vv = (k >> 5) % 5, ww = k & 31;
            int n = uu*5 + vv;
            float v = base[(size_t)ch*S_ + n*(H_*W_) + hh*W_ + ww];
            drow[k] = v;
            ss += v*v;
        }
    }
    __shared__ float red[256];
    red[t] = ss; __syncthreads();
    for (int st = 128; st > 0; st >>= 1) { if (t < st) red[t] += red[t + st]; __syncthreads(); }
    if (t == 0) ivd[row] = 1.f / fmaxf(sqrtf(red[0]), 1e-12f);
}

// ===================================================================
// 3a) SF raw scores: 128x64 tiles, 8x4 micro, double-buffered
// ===================================================================
__global__ __launch_bounds__(256) void k_score_sf() {
    int b = blockIdx.z, m0 = blockIdx.y*128, n0 = blockIdx.x*64;
    if (n0 > m0 + 127) return;
    const float* Ab = g_sfQ + (size_t)b*M_SF*K_SF;
    const float* Bb = g_sfK + (size_t)b*M_SF*K_SF;
    __shared__ __align__(16) float As[2][8][132];
    __shared__ __align__(16) float Bs[2][8][68];
    int t = threadIdx.x, tx = t & 15, ty = t >> 4;
    int lra = t >> 1, lca = (t & 1) * 4;
    int lrb = (t & 127) >> 1;
    float acc[8][4] = {};
    float4 av = *(const float4*)(Ab + (size_t)(m0+lra)*K_SF + lca);
    float4 bv = make_float4(0,0,0,0);
    if (t < 128) bv = *(const float4*)(Bb + (size_t)(n0+lrb)*K_SF + lca);
    As[0][lca+0][lra]=av.x; As[0][lca+1][lra]=av.y; As[0][lca+2][lra]=av.z; As[0][lca+3][lra]=av.w;
    if (t < 128) {
        Bs[0][lca+0][lrb]=bv.x; Bs[0][lca+1][lrb]=bv.y; Bs[0][lca+2][lrb]=bv.z; Bs[0][lca+3][lrb]=bv.w;
    }
    __syncthreads();
    const int nit = K_SF/8;
    for (int it = 0; it < nit; it++) {
        int cur = it & 1;
        if (it + 1 < nit) {
            int k0 = (it+1)*8;
            av = *(const float4*)(Ab + (size_t)(m0+lra)*K_SF + k0 + lca);
            if (t < 128) bv = *(const float4*)(Bb + (size_t)(n0+lrb)*K_SF + k0 + lca);
        }
        MICRO84(As[cur], Bs[cur]);
        if (it + 1 < nit) {
            int nx = cur^1;
            As[nx][lca+0][lra]=av.x; As[nx][lca+1][lra]=av.y; As[nx][lca+2][lra]=av.z; As[nx][lca+3][lra]=av.w;
            if (t < 128) {
                Bs[nx][lca+0][lrb]=bv.x; Bs[nx][lca+1][lrb]=bv.y; Bs[nx][lca+2][lrb]=bv.z; Bs[nx][lca+3][lrb]=bv.w;
            }
            __syncthreads();
        }
    }
    float* att = g_att + (size_t)b*M_SF*M_SF;
    #pragma unroll
    for (int i = 0; i < 8; i++) {
        int m = m0 + ty*4 + (i < 4 ? i : i + 60);
        *(float4*)(att + (size_t)m*M_SF + n0 + tx*4) =
            make_float4(acc[i][0], acc[i][1], acc[i][2], acc[i][3]);
    }
}

// ===================================================================
// 4a) SF softmax (scale + mask + softmax, register-resident)
// ===================================================================
__global__ __launch_bounds__(256) void k_softmax_sf() {
    int blk = blockIdx.x;
    int b = blk >> 10, m = blk & 1023;
    float* p = g_att + ((size_t)b*M_SF + m)*M_SF;
    int LIMW = ((m >> 7) + 1) << 7;
    float qn = g_ivq_sf[b*M_SF + m];
    const float* ivk = g_ivk_sf + b*M_SF;
    int t = threadIdx.x;
    __shared__ float red[256];
    float vv[4];
    float mx = -3.4e38f;
    #pragma unroll
    for (int i = 0; i < 4; i++) {
        int k = t + i*256;
        if (k < LIMW) {
            float v = (k <= m) ? p[k]*qn*ivk[k] : -3.4e38f;
            vv[i] = v; mx = fmaxf(mx, v);
        }
    }
    red[t] = mx; __syncthreads();
    for (int st = 128; st > 0; st >>= 1) { if (t < st) red[t] = fmaxf(red[t], red[t+st]); __syncthreads(); }
    mx = red[0]; __syncthreads();
    float s = 0.f;
    #pragma unroll
    for (int i = 0; i < 4; i++) {
        int k = t + i*256;
        if (k < LIMW) {
            float e = (k <= m) ? expf(vv[i] - mx) : 0.f;
            vv[i] = e; s += e;
        }
    }
    red[t] = s; __syncthreads();
    for (int st = 128; st > 0; st >>= 1) { if (t < st) red[t] += red[t+st]; __syncthreads(); }
    float inv = 1.f / red[0];
    #pragma unroll
    for (int i = 0; i < 4; i++) {
        int k = t + i*256;
        if (k < LIMW) p[k] = vv[i]*inv;
    }
}

// ===================================================================
// 5a) SF O = P @ V : 128x64 tiles, 8x4 micro, double-buffered, causal bound
// ===================================================================
__global__ __launch_bounds__(256) void k_pv_sf() {
    int b = blockIdx.z, m0 = blockIdx.y*128, k0 = blockIdx.x*64;
    const float* Pb = g_att + (size_t)b*M_SF*M_SF;
    const float* Vb = g_sfK + (size_t)b*M_SF*K_SF;
    __shared__ __align__(16) float As[2][8][132];
    __shared__ __align__(16) float Bs[2][8][68];
    int t = threadIdx.x, tx = t & 15, ty = t >> 4;
    int lra = t >> 1, lca = (t & 1) * 4;
    int vr = (t & 127) >> 4, vc = (t & 15) * 4;
    bool bval = (t < 128) && (k0 + vc < K_SF);
    float acc[8][4] = {};
    float4 av = *(const float4*)(Pb + (size_t)(m0+lra)*M_SF + lca);
    float4 bv = make_float4(0,0,0,0);
    if (bval) bv = *(const float4*)(Vb + (size_t)vr*K_SF + k0 + vc);
    As[0][lca+0][lra]=av.x; As[0][lca+1][lra]=av.y; As[0][lca+2][lra]=av.z; As[0][lca+3][lra]=av.w;
    if (t < 128) *(float4*)&Bs[0][vr][vc] = bv;
    __syncthreads();
    const int nit = (m0 + 128) / 8;
    for (int it = 0; it < nit; it++) {
        int cur = it & 1;
        if (it + 1 < nit) {
            int n0 = (it+1)*8;
            av = *(const float4*)(Pb + (size_t)(m0+lra)*M_SF + n0 + lca);
            if (bval) bv = *(const float4*)(Vb + (size_t)(n0+vr)*K_SF + k0 + vc);
        }
        MICRO84(As[cur], Bs[cur]);
        if (it + 1 < nit) {
            int nx = cur^1;
            As[nx][lca+0][lra]=av.x; As[nx][lca+1][lra]=av.y; As[nx][lca+2][lra]=av.z; As[nx][lca+3][lra]=av.w;
            if (t < 128) *(float4*)&Bs[nx][vr][vc] = bv;
            __syncthreads();
        }
    }
    float* O = g_sfO + (size_t)b*M_SF*K_SF;
    int c = k0 + tx*4;
    if (c < K_SF) {
        #pragma unroll
        for (int i = 0; i < 8; i++) {
            int m = m0 + ty*4 + (i < 4 ? i : i + 60);
            *(float4*)(O + (size_t)m*K_SF + c) =
                make_float4(acc[i][0], acc[i][1], acc[i][2], acc[i][3]);
        }
    }
}

// ===================================================================
// 3b) af/sa raw scores, split-K
// ===================================================================
template<int TYPE>
__global__ __launch_bounds__(256) void k_score_small() {
    constexpr int MM = 160;
    constexpr int KK = TYPE==1 ? K_AF : K_SA;
    constexpr int CH = TYPE==1 ? 8 : 16;
    constexpr int CHK = KK / CH;
    const float* Qf = TYPE==1 ? g_afQ : g_saQ;
    const float* Kf = TYPE==1 ? g_afK : g_saK;
    int z = blockIdx.z;
    int b = z / CH, ch = z % CH;
    int m0 = blockIdx.y*64, n0 = blockIdx.x*64;
    if (n0 > m0 + 63) return;
    const float* Ab = Qf + (size_t)b*MM*KK;
    const float* Bb = Kf + (size_t)b*MM*KK;
    __shared__ __align__(16) float As[16][64];
    __shared__ __align__(16) float Bs[16][64];
    int t = threadIdx.x, tn = t & 15, tm = t >> 4;
    int lr = t >> 2, lc = (t & 3) << 2;
    float acc[4][4] = {};
    int kbeg = ch*CHK, kend = kbeg + CHK;
    for (int k0 = kbeg; k0 < kend; k0 += 16) {
        float4 av = make_float4(0,0,0,0), bv = make_float4(0,0,0,0);
        if (m0 + lr < MM) av = *(const float4*)(Ab + (size_t)(m0+lr)*KK + k0 + lc);
        if (n0 + lr < MM) bv = *(const float4*)(Bb + (size_t)(n0+lr)*KK + k0 + lc);
        __syncthreads();
        As[lc+0][lr]=av.x; As[lc+1][lr]=av.y; As[lc+2][lr]=av.z; As[lc+3][lr]=av.w;
        Bs[lc+0][lr]=bv.x; Bs[lc+1][lr]=bv.y; Bs[lc+2][lr]=bv.z; Bs[lc+3][lr]=bv.w;
        __syncthreads();
        #pragma unroll
        for (int kk = 0; kk < 16; kk++) {
            float4 a = *(const float4*)&As[kk][tm << 2];
            float4 bq = *(const float4*)&Bs[kk][tn << 2];
            acc[0][0]+=a.x*bq.x; acc[0][1]+=a.x*bq.y; acc[0][2]+=a.x*bq.z; acc[0][3]+=a.x*bq.w;
            acc[1][0]+=a.y*bq.x; acc[1][1]+=a.y*bq.y; acc[1][2]+=a.y*bq.z; acc[1][3]+=a.y*bq.w;
            acc[2][0]+=a.z*bq.x; acc[2][1]+=a.z*bq.y; acc[2][2]+=a.z*bq.z; acc[2][3]+=a.z*bq.w;
            acc[3][0]+=a.w*bq.x; acc[3][1]+=a.w*bq.y; acc[3][2]+=a.w*bq.z; acc[3][3]+=a.w*bq.w;
        }
    }
    float* part = g_att + ((size_t)(ch*B_ + b)*MM)*MM;
    #pragma unroll
    for (int i = 0; i < 4; i++) {
        int m = m0 + (tm<<2) + i; if (m >= MM) continue;
        #pragma unroll
        for (int j = 0; j < 4; j++) {
            int n = n0 + (tn<<2) + j; if (n >= MM) continue;
            part[(size_t)m*MM + n] = acc[i][j];
        }
    }
}

// ---------------- 4b) af/sa softmax over split-K partials ----------------
template<int TYPE>
__global__ __launch_bounds__(256) void k_softmax_small() {
    constexpr int MM = 160;
    constexpr int CH = TYPE==1 ? 8 : 16;
    const float* ivq = TYPE==1 ? g_ivq_af : g_ivq_sa;
    const float* ivk = TYPE==1 ? g_ivk_af : g_ivk_sa;
    int blk = blockIdx.x;
    int b = blk / MM, m = blk % MM;
    int t = threadIdx.x;
    float v = -3.4e38f;
    if (t < MM && t <= m) {
        float s = 0.f;
        #pragma unroll 4
        for (int ch = 0; ch < CH; ch++)
            s += g_att[(((size_t)(ch*B_ + b))*MM + m)*MM + t];
        v = s * ivq[b*MM + m] * ivk[b*MM + t];
    }
    __shared__ float red[256];
    red[t] = v; __syncthreads();
    for (int st = 128; st > 0; st >>= 1) { if (t < st) red[t] = fmaxf(red[t], red[t+st]); __syncthreads(); }
    float mx = red[0]; __syncthreads();
    float e = (t < MM && t <= m) ? expf(v - mx) : 0.f;
    red[t] = e; __syncthreads();
    for (int st = 128; st > 0; st >>= 1) { if (t < st) red[t] += red[t+st]; __syncthreads(); }
    float inv = 1.f / red[0];
    if (t < MM) g_att[FOFF_ + ((size_t)b*MM + m)*MM + t] = e*inv;
}

// ---------------- 5b) af/sa O = P @ V ----------------
template<int TYPE>
__global__ __launch_bounds__(256) void k_pv() {
    constexpr int MM = 160;
    constexpr int KK = TYPE==1 ? K_AF : K_SA;
    const float* V = TYPE==1 ? g_afK : g_saK;
    float* O = TYPE==1 ? g_afO : g_saO;
    int b = blockIdx.z, m0 = blockIdx.y*64, k0 = blockIdx.x*64;
    int t = threadIdx.x, tn = t & 15, tm = t >> 4;
    const float* Pb = g_att + FOFF_ + (size_t)b*MM*MM;
    const float* Vb = V + (size_t)b*MM*KK;
    __shared__ __align__(16) float As[16][64];
    __shared__ __align__(16) float Bs[16][64];
    int lr = t >> 2, lc = (t & 3) << 2;
    int br = t >> 4, bc = (t & 15) << 2;
    float acc[4][4] = {};
    int NLIM = (m0 + 64 < MM) ? m0 + 64 : MM;
    for (int n0 = 0; n0 < NLIM; n0 += 16) {
        float4 av = make_float4(0,0,0,0), bv = make_float4(0,0,0,0);
        if (m0 + lr < MM) av = *(const float4*)(Pb + (size_t)(m0+lr)*MM + n0 + lc);
        if (n0 + br < MM) bv = *(const float4*)(Vb + (size_t)(n0+br)*KK + k0 + bc);
        __syncthreads();
        As[lc+0][lr]=av.x; As[lc+1][lr]=av.y; As[lc+2][lr]=av.z; As[lc+3][lr]=av.w;
        *(float4*)&Bs[br][bc] = bv;
        __syncthreads();
        #pragma unroll
        for (int nn = 0; nn < 16; nn++) {
            float4 a = *(const float4*)&As[nn][tm << 2];
            float4 bq = *(const float4*)&Bs[nn][tn << 2];
            acc[0][0]+=a.x*bq.x; acc[0][1]+=a.x*bq.y; acc[0][2]+=a.x*bq.z; acc[0][3]+=a.x*bq.w;
            acc[1][0]+=a.y*bq.x; acc[1][1]+=a.y*bq.y; acc[1][2]+=a.y*bq.z; acc[1][3]+=a.y*bq.w;
            acc[2][0]+=a.z*bq.x; acc[2][1]+=a.z*bq.y; acc[2][2]+=a.z*bq.z; acc[2][3]+=a.z*bq.w;
            acc[3][0]+=a.w*bq.x; acc[3][1]+=a.w*bq.y; acc[3][2]+=a.w*bq.z; acc[3][3]+=a.w*bq.w;
        }
    }
    #pragma unroll
    for (int i = 0; i < 4; i++) {
        int m = m0 + (tm<<2) + i; if (m >= MM) continue;
        #pragma unroll
        for (int j = 0; j < 4; j++) {
            int k = k0 + (tn<<2) + j;
            O[((size_t)b*MM + m)*KK + k] = acc[i][j];
        }
    }
}

// ===================================================================
// 6+7) fused unfold+residual+LayerNorm: block=256 covers 2 tokens
// ===================================================================
__global__ __launch_bounds__(256) void k_combine_ln(const float* __restrict__ gamma,
                                                    const float* __restrict__ beta) {
    int t = threadIdx.x;
    int tok = t >> 7;            // 0/1 within block
    int dc = t & 127;
    int T = blockIdx.x*2 + tok;
    int ww = T & 31, hh = (T >> 5) & 31;
    int bn = T >> 10;
    int b = bn / 25, n = bn % 25;
    int uu = n / 5, vv = n % 5;
    float r = g_kv[((size_t)b*D_ + dc)*S_ + n*(H_*W_) + hh*W_ + ww];
    float o;
    if (dc < 32) {
        int m = dc*32 + hh, k = n*32 + ww;
        o = g_sfO[((size_t)b*M_SF + m)*K_SF + k];
    } else if (dc < 64) {
        int m = (dc-32)*5 + uu, k = (hh*5 + vv)*32 + ww;
        o = g_afO[((size_t)b*M_AF + m)*K_AF + k];
    } else {
        int m = hh*5 + uu, k = ((dc-64)*5 + vv)*32 + ww;
        o = g_saO[((size_t)b*M_SA + m)*K_SA + k];
    }
    float v = o + r;
    g_ct[(size_t)T*D_ + dc] = v;
    // mean over 128 lanes (4 warps per token)
    float s = v;
    #pragma unroll
    for (int of = 16; of > 0; of >>= 1) s += __shfl_xor_sync(0xffffffffu, s, of);
    __shared__ float wsum[2][4];
    int wg = (t >> 5) & 3;
    if ((t & 31) == 0) wsum[tok][wg] = s;
    __syncthreads();
    float mu = (wsum[tok][0]+wsum[tok][1]+wsum[tok][2]+wsum[tok][3]) * (1.f/128.f);
    float cx = v - mu;
    float sq = cx*cx;
    #pragma unroll
    for (int of = 16; of > 0; of >>= 1) sq += __shfl_xor_sync(0xffffffffu, sq, of);
    __shared__ float wsq[2][4];
    if ((t & 31) == 0) wsq[tok][wg] = sq;
    __syncthreads();
    float var = (wsq[tok][0]+wsq[tok][1]+wsq[tok][2]+wsq[tok][3]) * (1.f/128.f);
    float inv = rsqrtf(var + 1e-5f);
    g_ln[(size_t)T*D_ + dc] = cx*inv*gamma[dc] + beta[dc];
}

// ===================================================================
// 8) MLP gemms: 128-row tiles, 8x8 micro, double-buffered
// ===================================================================
template<int MODE>
__global__ __launch_bounds__(256) void k_mlp_big(const float* __restrict__ Wm,
                                                 float* __restrict__ outp) {
    constexpr int NOUT = (MODE == 2) ? 64 : 128;
    const float* A = (MODE == 1) ? g_h1 : g_ln;
    int m0 = blockIdx.x * 128;
    __shared__ __align__(16) float As[2][8][132];
    __shared__ __align__(16) float Bs[2][8][132];
    int t = threadIdx.x, tx = t & 15, ty = t >> 4;
    int lrow = t >> 1, lcol = (t & 1) * 4;
    int vrow = t >> 5, vcol = (t & 31) * 4;
    float acc[8][8] = {};
    float4 av = *(const float4*)(A + (size_t)(m0+lrow)*D_ + lcol);
    if (MODE == 2) {
        float4 a2 = *(const float4*)(g_ct + (size_t)(m0+lrow)*D_ + lcol);
        av.x += a2.x; av.y += a2.y; av.z += a2.z; av.w += a2.w;
    }
    float4 bv = make_float4(0,0,0,0);
    if (vcol < NOUT) bv = *(const float4*)(Wm + (size_t)vrow*NOUT + vcol);
    As[0][lcol+0][lrow]=av.x; As[0][lcol+1][lrow]=av.y; As[0][lcol+2][lrow]=av.z; As[0][lcol+3][lrow]=av.w;
    *(float4*)&Bs[0][vrow][vcol] = bv;
    __syncthreads();
    const int nit = 16;
    for (int it = 0; it < nit; it++) {
        int cur = it & 1;
        if (it + 1 < nit) {
            int k0 = (it+1)*8;
            av = *(const float4*)(A + (size_t)(m0+lrow)*D_ + k0 + lcol);
            if (MODE == 2) {
                float4 a2 = *(const float4*)(g_ct + (size_t)(m0+lrow)*D_ + k0 + lcol);
                av.x += a2.x; av.y += a2.y; av.z += a2.z; av.w += a2.w;
            }
            if (vcol < NOUT) bv = *(const float4*)(Wm + (size_t)(k0+vrow)*NOUT + vcol);
        }
        MICRO88(As[cur], Bs[cur]);
        if (it + 1 < nit) {
            int nx = cur^1;
            As[nx][lcol+0][lrow]=av.x; As[nx][lcol+1][lrow]=av.y; As[nx][lcol+2][lrow]=av.z; As[nx][lcol+3][lrow]=av.w;
            *(float4*)&Bs[nx][vrow][vcol] = bv;
            __syncthreads();
        }
    }
    if (MODE == 2) {
        #pragma unroll
        for (int j = 0; j < 4; j++) {
            int nn = tx*4 + j;
            int m = m0 + ty*4;
            int ww = m & 31, hh = (m >> 5) & 31;
            int bn = m >> 10; int b = bn / 25, na = bn % 25;
            float* ob = outp + ((size_t)b*C_ + nn)*S_ + na*(H_*W_) + hh*W_ + ww;
            *(float4*)ob = make_float4(acc[0][j], acc[1][j], acc[2][j], acc[3][j]);
            int m2 = m + 64;
            int ww2 = m2 & 31, hh2 = (m2 >> 5) & 31;
            int bn2 = m2 >> 10; int b2 = bn2 / 25, na2 = bn2 % 25;
            float* ob2 = outp + ((size_t)b2*C_ + nn)*S_ + na2*(H_*W_) + hh2*W_ + ww2;
            *(float4*)ob2 = make_float4(acc[4][j], acc[5][j], acc[6][j], acc[7][j]);
        }
    } else {
        float* dst = (MODE == 0) ? g_h1 : g_ln;
        #pragma unroll
        for (int i = 0; i < 8; i++) {
            int m = m0 + ty*4 + (i < 4 ? i : i + 60);
            float4 v0 = make_float4(acc[i][0],acc[i][1],acc[i][2],acc[i][3]);
            float4 v1 = make_float4(acc[i][4],acc[i][5],acc[i][6],acc[i][7]);
            if (MODE == 0) {
                v0.x=fmaxf(v0.x,0.f); v0.y=fmaxf(v0.y,0.f); v0.z=fmaxf(v0.z,0.f); v0.w=fmaxf(v0.w,0.f);
                v1.x=fmaxf(v1.x,0.f); v1.y=fmaxf(v1.y,0.f); v1.z=fmaxf(v1.z,0.f); v1.w=fmaxf(v1.w,0.f);
            }
            *(float4*)(dst + (size_t)m*D_ + tx*4)      = v0;
            *(float4*)(dst + (size_t)m*D_ + tx*4 + 64) = v1;
        }
    }
}

// ---------------- launch ----------------
extern "C" void kernel_launch(void* const* d_in, const int* in_sizes, int n_in,
                              void* d_out, int out_size) {
    const float* x_lf = (const float*)d_in[0];
    const float* x_hf = (const float*)d_in[1];
    const float* W_in = (const float*)d_in[2];
    const float* W_kv = (const float*)d_in[3];
    const float* ln_g = (const float*)d_in[4];
    const float* ln_b = (const float*)d_in[5];
    const float* W_m1 = (const float*)d_in[6];
    const float* W_m2 = (const float*)d_in[7];
    const float* W_ot = (const float*)d_in[8];
    float* out = (float*)d_out;

    k_tokens_big<0><<<NPOS_/128, 256>>>(x_hf, W_in);
    k_tokens_big<1><<<NPOS_/128, 256>>>(x_lf, W_kv);

    // sf attention
    k_fold<0><<<dim3(B_*M_SF, 2), 256>>>();
    k_score_sf<<<dim3(M_SF/64, M_SF/128, B_), 256>>>();
    k_softmax_sf<<<B_*M_SF, 256>>>();
    k_pv_sf<<<dim3((K_SF+63)/64, M_SF/128, B_), 256>>>();

    // af attention (split-K 8)
    k_fold<1><<<dim3(B_*M_AF, 2), 256>>>();
    k_score_small<1><<<dim3(3, 3, B_*8), 256>>>();
    k_softmax_small<1><<<B_*M_AF, 256>>>();
    k_pv<1><<<dim3(K_AF/64, 3, B_), 256>>>();

    // sa attention (split-K 16)
    k_fold<2><<<dim3(B_*M_SA, 2), 256>>>();
    k_score_small<2><<<dim3(3, 3, B_*16), 256>>>();
    k_softmax_small<2><<<B_*M_SA, 256>>>();
    k_pv<2><<<dim3(K_SA/64, 3, B_), 256>>>();

    // fused combine+LN, then MLP
    k_combine_ln<<<NPOS_/2, 256>>>(ln_g, ln_b);
    k_mlp_big<0><<<NPOS_/128, 256>>>(W_m1, nullptr);
    k_mlp_big<1><<<NPOS_/128, 256>>>(W_m2, nullptr);
    k_mlp_big<2><<<NPOS_/128, 256>>>(W_ot, out);
}

// round 7
// speedup vs baseline: 2.2114x; 1.0987x over previous
#include <cuda_runtime.h>
#include <mma.h>
using namespace nvcuda;

// ---------------- problem constants ----------------
#define B_    4
#define C_    64
#define NA_   25
#define D_    128
#define H_    32
#define W_    32
#define S_    25600      // NA*H*W
#define NPOS_ 102400     // B*S
#define M_SF  1024
#define K_SF  800
#define M_AF  160
#define K_AF  5120
#define M_SA  160
#define K_SA  10240
#define FOFF_ (16*B_*M_AF*M_AF)

// ---------------- scratch (device globals; no allocation) ----------------
__device__ float g_q [B_*D_*S_];
__device__ float g_kv[B_*D_*S_];

__device__ float g_sfQ[B_*M_SF*K_SF];
__device__ float g_sfK[B_*M_SF*K_SF];
__device__ float g_sfO[B_*M_SF*K_SF];
__device__ float g_afQ[B_*M_AF*K_AF];
__device__ float g_afK[B_*M_AF*K_AF];
__device__ float g_afO[B_*M_AF*K_AF];
__device__ float g_saQ[B_*M_SA*K_SA];
__device__ float g_saK[B_*M_SA*K_SA];
__device__ float g_saO[B_*M_SA*K_SA];

__device__ float g_ivq_sf[B_*M_SF];
__device__ float g_ivk_sf[B_*M_SF];
__device__ float g_ivq_af[B_*M_AF];
__device__ float g_ivk_af[B_*M_AF];
__device__ float g_ivq_sa[B_*M_SA];
__device__ float g_ivk_sa[B_*M_SA];

__device__ float g_att[B_*M_SF*M_SF];

__device__ float g_ct[NPOS_*D_];
__device__ float g_ln[NPOS_*D_];
__device__ float g_h1[NPOS_*D_];

// ---------------- wmma tf32 helpers ----------------
using FragAr = wmma::fragment<wmma::matrix_a, 16,16,8, wmma::precision::tf32, wmma::row_major>;
using FragAc = wmma::fragment<wmma::matrix_a, 16,16,8, wmma::precision::tf32, wmma::col_major>;
using FragBr = wmma::fragment<wmma::matrix_b, 16,16,8, wmma::precision::tf32, wmma::row_major>;
using FragBc = wmma::fragment<wmma::matrix_b, 16,16,8, wmma::precision::tf32, wmma::col_major>;
using FragC  = wmma::fragment<wmma::accumulator, 16,16,8, float>;

template<class F> __device__ __forceinline__ void cvt_tf32(F& f) {
    #pragma unroll
    for (int i = 0; i < f.num_elements; i++) f.x[i] = wmma::__float_to_tf32(f.x[i]);
}

// ===================================================================
// 1) token projection: y[(b,dc),s] = sum_c x[(b,c),s] * W[c,dc]
//    A col-major straight from global; output stored col-major to global.
// ===================================================================
template<int WHICH>
__global__ __launch_bounds__(256) void k_tokens_wmma(const float* __restrict__ x,
                                                     const float* __restrict__ Wm) {
    float* y = (WHICH == 0) ? g_q : g_kv;
    int m0 = blockIdx.x * 128;
    int b = m0 / S_, s0 = m0 % S_;
    const float* xb = x + (size_t)b*C_*S_ + s0;
    int wid = threadIdx.x >> 5, wm = wid & 1, wn = wid >> 1;
    FragC acc[4][2];
    #pragma unroll
    for (int f = 0; f < 4; f++)
        #pragma unroll
        for (int j = 0; j < 2; j++) wmma::fill_fragment(acc[f][j], 0.f);
    for (int k = 0; k < C_; k += 8) {
        FragBr bf[2];
        #pragma unroll
        for (int j = 0; j < 2; j++) {
            wmma::load_matrix_sync(bf[j], Wm + (size_t)k*D_ + wn*32 + j*16, D_);
            cvt_tf32(bf[j]);
        }
        #pragma unroll
        for (int f = 0; f < 4; f++) {
            FragAc af;
            wmma::load_matrix_sync(af, xb + (size_t)k*S_ + wm*64 + f*16, S_);
            cvt_tf32(af);
            #pragma unroll
            for (int j = 0; j < 2; j++) wmma::mma_sync(acc[f][j], af, bf[j], acc[f][j]);
        }
    }
    float* yb = y + (size_t)b*D_*S_ + s0;
    #pragma unroll
    for (int f = 0; f < 4; f++)
        #pragma unroll
        for (int j = 0; j < 2; j++)
            wmma::store_matrix_sync(yb + (size_t)(wn*32 + j*16)*S_ + wm*64 + f*16,
                                    acc[f][j], S_, wmma::mem_col_major);
}

// ---------------- 2) fold gather + inverse L2 norms ----------------
template<int TYPE>
__global__ void k_fold() {
    constexpr int MM  = TYPE==0 ? M_SF : (TYPE==1 ? M_AF : M_SA);
    constexpr int KK  = TYPE==0 ? K_SF : (TYPE==1 ? K_AF : K_SA);
    constexpr int OFF = TYPE==0 ? 0 : (TYPE==1 ? 32 : 64);
    int row = blockIdx.x;
    int isK = blockIdx.y;
    int b = row / MM, m = row % MM;
    const float* src = isK ? g_kv : g_q;
    float* dst; float* ivd;
    if (TYPE==0) { dst = isK ? g_sfK : g_sfQ; ivd = isK ? g_ivk_sf : g_ivq_sf; }
    else if (TYPE==1) { dst = isK ? g_afK : g_afQ; ivd = isK ? g_ivk_af : g_ivq_af; }
    else { dst = isK ? g_saK : g_saQ; ivd = isK ? g_ivk_sa : g_ivq_sa; }
    const float* base = src + ((size_t)b*D_ + OFF)*S_;
    float* drow = dst + (size_t)row*KK;
    int t = threadIdx.x;
    float ss = 0.f;
    if (TYPE == 0) {
        int ch = m >> 5, hh = m & 31;
        const float* bp = base + (size_t)ch*S_ + hh*W_;
        for (int kk = t; kk < KK; kk += 256) {
            int n = kk >> 5, ww = kk & 31;
            float v = bp[n*(H_*W_) + ww];
            drow[kk] = v;
            ss += v*v;
        }
    } else if (TYPE == 1) {
        int ch = m / 5, uu = m % 5;
        const float* bp = base + (size_t)ch*S_;
        for (int k = t; k < KK; k += 256) {
            int hh = k / 160, vv = (k >> 5) % 5, ww = k & 31;
            int n = uu*5 + vv;
            float v = bp[n*(H_*W_) + hh*W_ + ww];
            drow[k] = v;
            ss += v*v;
        }
    } else {
        int hh = m / 5, uu = m % 5;
        for (int k = t; k < KK; k += 256) {
            int ch = k / 160, vv = (k >> 5) % 5, ww = k & 31;
            int n = uu*5 + vv;
            float v = base[(size_t)ch*S_ + n*(H_*W_) + hh*W_ + ww];
            drow[k] = v;
            ss += v*v;
        }
    }
    __shared__ float red[256];
    red[t] = ss; __syncthreads();
    for (int st = 128; st > 0; st >>= 1) { if (t < st) red[t] += red[t + st]; __syncthreads(); }
    if (t == 0) ivd[row] = 1.f / fmaxf(sqrtf(red[0]), 1e-12f);
}

// ===================================================================
// 3a) SF raw scores (NT), wmma tf32: 128x64 tiles, 8 warps (2m x 4n)
// ===================================================================
__global__ __launch_bounds__(256) void k_score_sf() {
    int b = blockIdx.z, m0 = blockIdx.y*128, n0 = blockIdx.x*64;
    if (n0 > m0 + 127) return;
    const float* Ab = g_sfQ + (size_t)b*M_SF*K_SF;
    const float* Bb = g_sfK + (size_t)b*M_SF*K_SF;
    __shared__ __align__(16) float As[2][128][20];
    __shared__ __align__(16) float Bs[2][64][20];
    int t = threadIdx.x;
    int wid = t >> 5, wm = wid & 1, wn = wid >> 1;
    int ar_ = t >> 1, ac_ = (t & 1) * 8;
    int br_ = t >> 2, bc_ = (t & 3) * 4;
    FragC acc[4];
    #pragma unroll
    for (int i = 0; i < 4; i++) wmma::fill_fragment(acc[i], 0.f);
    float4 a0 = *(const float4*)(Ab + (size_t)(m0+ar_)*K_SF + ac_);
    float4 a1 = *(const float4*)(Ab + (size_t)(m0+ar_)*K_SF + ac_ + 4);
    float4 b0 = *(const float4*)(Bb + (size_t)(n0+br_)*K_SF + bc_);
    *(float4*)&As[0][ar_][ac_]   = a0;
    *(float4*)&As[0][ar_][ac_+4] = a1;
    *(float4*)&Bs[0][br_][bc_]   = b0;
    __syncthreads();
    const int nit = K_SF/16;
    for (int it = 0; it < nit; it++) {
        int cur = it & 1;
        if (it + 1 < nit) {
            int k0 = (it+1)*16;
            a0 = *(const float4*)(Ab + (size_t)(m0+ar_)*K_SF + k0 + ac_);
            a1 = *(const float4*)(Ab + (size_t)(m0+ar_)*K_SF + k0 + ac_ + 4);
            b0 = *(const float4*)(Bb + (size_t)(n0+br_)*K_SF + k0 + bc_);
        }
        #pragma unroll
        for (int ks = 0; ks < 16; ks += 8) {
            FragBc bf;
            wmma::load_matrix_sync(bf, &Bs[cur][wn*16][ks], 20);
            cvt_tf32(bf);
            #pragma unroll
            for (int f = 0; f < 4; f++) {
                FragAr af;
                wmma::load_matrix_sync(af, &As[cur][wm*64 + f*16][ks], 20);
                cvt_tf32(af);
                wmma::mma_sync(acc[f], af, bf, acc[f]);
            }
        }
        if (it + 1 < nit) {
            int nx = cur ^ 1;
            *(float4*)&As[nx][ar_][ac_]   = a0;
            *(float4*)&As[nx][ar_][ac_+4] = a1;
            *(float4*)&Bs[nx][br_][bc_]   = b0;
            __syncthreads();
        }
    }
    float* att = g_att + (size_t)b*M_SF*M_SF;
    #pragma unroll
    for (int f = 0; f < 4; f++)
        wmma::store_matrix_sync(att + (size_t)(m0 + wm*64 + f*16)*M_SF + n0 + wn*16,
                                acc[f], M_SF, wmma::mem_row_major);
}

// ===================================================================
// 4a) SF softmax (scale + mask + softmax, register-resident)
// ===================================================================
__global__ __launch_bounds__(256) void k_softmax_sf() {
    int blk = blockIdx.x;
    int b = blk >> 10, m = blk & 1023;
    float* p = g_att + ((size_t)b*M_SF + m)*M_SF;
    int LIMW = ((m >> 7) + 1) << 7;
    float qn = g_ivq_sf[b*M_SF + m];
    const float* ivk = g_ivk_sf + b*M_SF;
    int t = threadIdx.x;
    __shared__ float red[256];
    float vv[4];
    float mx = -3.4e38f;
    #pragma unroll
    for (int i = 0; i < 4; i++) {
        int k = t + i*256;
        if (k < LIMW) {
            float v = (k <= m) ? p[k]*qn*ivk[k] : -3.4e38f;
            vv[i] = v; mx = fmaxf(mx, v);
        }
    }
    red[t] = mx; __syncthreads();
    for (int st = 128; st > 0; st >>= 1) { if (t < st) red[t] = fmaxf(red[t], red[t+st]); __syncthreads(); }
    mx = red[0]; __syncthreads();
    float s = 0.f;
    #pragma unroll
    for (int i = 0; i < 4; i++) {
        int k = t + i*256;
        if (k < LIMW) {
            float e = (k <= m) ? expf(vv[i] - mx) : 0.f;
            vv[i] = e; s += e;
        }
    }
    red[t] = s; __syncthreads();
    for (int st = 128; st > 0; st >>= 1) { if (t < st) red[t] += red[t+st]; __syncthreads(); }
    float inv = 1.f / red[0];
    #pragma unroll
    for (int i = 0; i < 4; i++) {
        int k = t + i*256;
        if (k < LIMW) p[k] = vv[i]*inv;
    }
}

// ===================================================================
// 5a) SF O = P @ V (NN), wmma tf32: 128x64 tiles, causal bound
// ===================================================================
__global__ __launch_bounds__(256) void k_pv_sf() {
    int b = blockIdx.z, m0 = blockIdx.y*128, k0 = blockIdx.x*64;
    const float* Pb = g_att + (size_t)b*M_SF*M_SF;
    const float* Vb = g_sfK + (size_t)b*M_SF*K_SF;
    __shared__ __align__(16) float As[2][128][20];
    __shared__ __align__(16) float Bs[2][16][68];
    int t = threadIdx.x;
    int wid = t >> 5, wm = wid & 1, wn = wid >> 1;
    int ar_ = t >> 1, ac_ = (t & 1) * 8;
    int vr_ = t >> 4, vc_ = (t & 15) * 4;
    bool bok = (k0 + vc_) < K_SF;
    FragC acc[4];
    #pragma unroll
    for (int i = 0; i < 4; i++) wmma::fill_fragment(acc[i], 0.f);
    float4 a0 = *(const float4*)(Pb + (size_t)(m0+ar_)*M_SF + ac_);
    float4 a1 = *(const float4*)(Pb + (size_t)(m0+ar_)*M_SF + ac_ + 4);
    float4 b0 = bok ? *(const float4*)(Vb + (size_t)vr_*K_SF + k0 + vc_) : make_float4(0,0,0,0);
    *(float4*)&As[0][ar_][ac_]   = a0;
    *(float4*)&As[0][ar_][ac_+4] = a1;
    *(float4*)&Bs[0][vr_][vc_]   = b0;
    __syncthreads();
    const int nit = (m0 + 128) / 16;
    for (int it = 0; it < nit; it++) {
        int cur = it & 1;
        if (it + 1 < nit) {
            int n0 = (it+1)*16;
            a0 = *(const float4*)(Pb + (size_t)(m0+ar_)*M_SF + n0 + ac_);
            a1 = *(const float4*)(Pb + (size_t)(m0+ar_)*M_SF + n0 + ac_ + 4);
            b0 = bok ? *(const float4*)(Vb + (size_t)(n0+vr_)*K_SF + k0 + vc_) : make_float4(0,0,0,0);
        }
        #pragma unroll
        for (int ks = 0; ks < 16; ks += 8) {
            FragBr bf;
            wmma::load_matrix_sync(bf, &Bs[cur][ks][wn*16], 68);
            cvt_tf32(bf);
            #pragma unroll
            for (int f = 0; f < 4; f++) {
                FragAr af;
                wmma::load_matrix_sync(af, &As[cur][wm*64 + f*16][ks], 20);
                cvt_tf32(af);
                wmma::mma_sync(acc[f], af, bf, acc[f]);
            }
        }
        if (it + 1 < nit) {
            int nx = cur ^ 1;
            *(float4*)&As[nx][ar_][ac_]   = a0;
            *(float4*)&As[nx][ar_][ac_+4] = a1;
            *(float4*)&Bs[nx][vr_][vc_]   = b0;
            __syncthreads();
        }
    }
    float* O = g_sfO + (size_t)b*M_SF*K_SF;
    int col0 = k0 + wn*16;
    if (col0 < K_SF) {
        #pragma unroll
        for (int f = 0; f < 4; f++)
            wmma::store_matrix_sync(O + (size_t)(m0 + wm*64 + f*16)*K_SF + col0,
                                    acc[f], K_SF, wmma::mem_row_major);
    }
}

// ===================================================================
// 3b) af/sa raw scores, split-K (SIMT; small)
// ===================================================================
template<int TYPE>
__global__ __launch_bounds__(256) void k_score_small() {
    constexpr int MM = 160;
    constexpr int KK = TYPE==1 ? K_AF : K_SA;
    constexpr int CH = TYPE==1 ? 8 : 16;
    constexpr int CHK = KK / CH;
    const float* Qf = TYPE==1 ? g_afQ : g_saQ;
    const float* Kf = TYPE==1 ? g_afK : g_saK;
    int z = blockIdx.z;
    int b = z / CH, ch = z % CH;
    int m0 = blockIdx.y*64, n0 = blockIdx.x*64;
    if (n0 > m0 + 63) return;
    const float* Ab = Qf + (size_t)b*MM*KK;
    const float* Bb = Kf + (size_t)b*MM*KK;
    __shared__ __align__(16) float As[16][64];
    __shared__ __align__(16) float Bs[16][64];
    int t = threadIdx.x, tn = t & 15, tm = t >> 4;
    int lr = t >> 2, lc = (t & 3) << 2;
    float acc[4][4] = {};
    int kbeg = ch*CHK, kend = kbeg + CHK;
    for (int k0 = kbeg; k0 < kend; k0 += 16) {
        float4 av = make_float4(0,0,0,0), bv = make_float4(0,0,0,0);
        if (m0 + lr < MM) av = *(const float4*)(Ab + (size_t)(m0+lr)*KK + k0 + lc);
        if (n0 + lr < MM) bv = *(const float4*)(Bb + (size_t)(n0+lr)*KK + k0 + lc);
        __syncthreads();
        As[lc+0][lr]=av.x; As[lc+1][lr]=av.y; As[lc+2][lr]=av.z; As[lc+3][lr]=av.w;
        Bs[lc+0][lr]=bv.x; Bs[lc+1][lr]=bv.y; Bs[lc+2][lr]=bv.z; Bs[lc+3][lr]=bv.w;
        __syncthreads();
        #pragma unroll
        for (int kk = 0; kk < 16; kk++) {
            float4 a = *(const float4*)&As[kk][tm << 2];
            float4 bq = *(const float4*)&Bs[kk][tn << 2];
            acc[0][0]+=a.x*bq.x; acc[0][1]+=a.x*bq.y; acc[0][2]+=a.x*bq.z; acc[0][3]+=a.x*bq.w;
            acc[1][0]+=a.y*bq.x; acc[1][1]+=a.y*bq.y; acc[1][2]+=a.y*bq.z; acc[1][3]+=a.y*bq.w;
            acc[2][0]+=a.z*bq.x; acc[2][1]+=a.z*bq.y; acc[2][2]+=a.z*bq.z; acc[2][3]+=a.z*bq.w;
            acc[3][0]+=a.w*bq.x; acc[3][1]+=a.w*bq.y; acc[3][2]+=a.w*bq.z; acc[3][3]+=a.w*bq.w;
        }
    }
    float* part = g_att + ((size_t)(ch*B_ + b)*MM)*MM;
    #pragma unroll
    for (int i = 0; i < 4; i++) {
        int m = m0 + (tm<<2) + i; if (m >= MM) continue;
        #pragma unroll
        for (int j = 0; j < 4; j++) {
            int n = n0 + (tn<<2) + j; if (n >= MM) continue;
            part[(size_t)m*MM + n] = acc[i][j];
        }
    }
}

// ---------------- 4b) af/sa softmax over split-K partials ----------------
template<int TYPE>
__global__ __launch_bounds__(256) void k_softmax_small() {
    constexpr int MM = 160;
    constexpr int CH = TYPE==1 ? 8 : 16;
    const float* ivq = TYPE==1 ? g_ivq_af : g_ivq_sa;
    const float* ivk = TYPE==1 ? g_ivk_af : g_ivk_sa;
    int blk = blockIdx.x;
    int b = blk / MM, m = blk % MM;
    int t = threadIdx.x;
    float v = -3.4e38f;
    if (t < MM && t <= m) {
        float s = 0.f;
        #pragma unroll 4
        for (int ch = 0; ch < CH; ch++)
            s += g_att[(((size_t)(ch*B_ + b))*MM + m)*MM + t];
        v = s * ivq[b*MM + m] * ivk[b*MM + t];
    }
    __shared__ float red[256];
    red[t] = v; __syncthreads();
    for (int st = 128; st > 0; st >>= 1) { if (t < st) red[t] = fmaxf(red[t], red[t+st]); __syncthreads(); }
    float mx = red[0]; __syncthreads();
    float e = (t < MM && t <= m) ? expf(v - mx) : 0.f;
    red[t] = e; __syncthreads();
    for (int st = 128; st > 0; st >>= 1) { if (t < st) red[t] += red[t+st]; __syncthreads(); }
    float inv = 1.f / red[0];
    if (t < MM) g_att[FOFF_ + ((size_t)b*MM + m)*MM + t] = e*inv;
}

// ---------------- 5b) af/sa O = P @ V (SIMT) ----------------
template<int TYPE>
__global__ __launch_bounds__(256) void k_pv() {
    constexpr int MM = 160;
    constexpr int KK = TYPE==1 ? K_AF : K_SA;
    const float* V = TYPE==1 ? g_afK : g_saK;
    float* O = TYPE==1 ? g_afO : g_saO;
    int b = blockIdx.z, m0 = blockIdx.y*64, k0 = blockIdx.x*64;
    int t = threadIdx.x, tn = t & 15, tm = t >> 4;
    const float* Pb = g_att + FOFF_ + (size_t)b*MM*MM;
    const float* Vb = V + (size_t)b*MM*KK;
    __shared__ __align__(16) float As[16][64];
    __shared__ __align__(16) float Bs[16][64];
    int lr = t >> 2, lc = (t & 3) << 2;
    int br = t >> 4, bc = (t & 15) << 2;
    float acc[4][4] = {};
    int NLIM = (m0 + 64 < MM) ? m0 + 64 : MM;
    for (int n0 = 0; n0 < NLIM; n0 += 16) {
        float4 av = make_float4(0,0,0,0), bv = make_float4(0,0,0,0);
        if (m0 + lr < MM) av = *(const float4*)(Pb + (size_t)(m0+lr)*MM + n0 + lc);
        if (n0 + br < MM) bv = *(const float4*)(Vb + (size_t)(n0+br)*KK + k0 + bc);
        __syncthreads();
        As[lc+0][lr]=av.x; As[lc+1][lr]=av.y; As[lc+2][lr]=av.z; As[lc+3][lr]=av.w;
        *(float4*)&Bs[br][bc] = bv;
        __syncthreads();
        #pragma unroll
        for (int nn = 0; nn < 16; nn++) {
            float4 a = *(const float4*)&As[nn][tm << 2];
            float4 bq = *(const float4*)&Bs[nn][tn << 2];
            acc[0][0]+=a.x*bq.x; acc[0][1]+=a.x*bq.y; acc[0][2]+=a.x*bq.z; acc[0][3]+=a.x*bq.w;
            acc[1][0]+=a.y*bq.x; acc[1][1]+=a.y*bq.y; acc[1][2]+=a.y*bq.z; acc[1][3]+=a.y*bq.w;
            acc[2][0]+=a.z*bq.x; acc[2][1]+=a.z*bq.y; acc[2][2]+=a.z*bq.z; acc[2][3]+=a.z*bq.w;
            acc[3][0]+=a.w*bq.x; acc[3][1]+=a.w*bq.y; acc[3][2]+=a.w*bq.z; acc[3][3]+=a.w*bq.w;
        }
    }
    #pragma unroll
    for (int i = 0; i < 4; i++) {
        int m = m0 + (tm<<2) + i; if (m >= MM) continue;
        #pragma unroll
        for (int j = 0; j < 4; j++) {
            int k = k0 + (tn<<2) + j;
            O[((size_t)b*MM + m)*KK + k] = acc[i][j];
        }
    }
}

// ===================================================================
// 6+7) fused unfold+residual+LayerNorm: block=256 covers 2 tokens
// ===================================================================
__global__ __launch_bounds__(256) void k_combine_ln(const float* __restrict__ gamma,
                                                    const float* __restrict__ beta) {
    int t = threadIdx.x;
    int tok = t >> 7;
    int dc = t & 127;
    int T = blockIdx.x*2 + tok;
    int ww = T & 31, hh = (T >> 5) & 31;
    int bn = T >> 10;
    int b = bn / 25, n = bn % 25;
    int uu = n / 5, vv = n % 5;
    float r = g_kv[((size_t)b*D_ + dc)*S_ + n*(H_*W_) + hh*W_ + ww];
    float o;
    if (dc < 32) {
        int m = dc*32 + hh, k = n*32 + ww;
        o = g_sfO[((size_t)b*M_SF + m)*K_SF + k];
    } else if (dc < 64) {
        int m = (dc-32)*5 + uu, k = (hh*5 + vv)*32 + ww;
        o = g_afO[((size_t)b*M_AF + m)*K_AF + k];
    } else {
        int m = hh*5 + uu, k = ((dc-64)*5 + vv)*32 + ww;
        o = g_saO[((size_t)b*M_SA + m)*K_SA + k];
    }
    float v = o + r;
    g_ct[(size_t)T*D_ + dc] = v;
    float s = v;
    #pragma unroll
    for (int of = 16; of > 0; of >>= 1) s += __shfl_xor_sync(0xffffffffu, s, of);
    __shared__ float wsum[2][4];
    int wg = (t >> 5) & 3;
    if ((t & 31) == 0) wsum[tok][wg] = s;
    __syncthreads();
    float mu = (wsum[tok][0]+wsum[tok][1]+wsum[tok][2]+wsum[tok][3]) * (1.f/128.f);
    float cx = v - mu;
    float sq = cx*cx;
    #pragma unroll
    for (int of = 16; of > 0; of >>= 1) sq += __shfl_xor_sync(0xffffffffu, sq, of);
    __shared__ float wsq[2][4];
    if ((t & 31) == 0) wsq[tok][wg] = sq;
    __syncthreads();
    float var = (wsq[tok][0]+wsq[tok][1]+wsq[tok][2]+wsq[tok][3]) * (1.f/128.f);
    float inv = rsqrtf(var + 1e-5f);
    g_ln[(size_t)T*D_ + dc] = cx*inv*gamma[dc] + beta[dc];
}

// ===================================================================
// 8) MLP gemms, wmma tf32: 128-row tiles. B frags straight from global W.
// MODE 0: h1 = relu(ln@W_m1)  MODE 1: ln <- h1@W_m2  MODE 2: out=(ln+ct)@W_out
// ===================================================================
template<int MODE>
__global__ __launch_bounds__(256) void k_mlp_wmma(const float* __restrict__ Wm,
                                                  float* __restrict__ outp) {
    constexpr int NOUT = (MODE == 2) ? 64 : 128;
    constexpr int NF   = (MODE == 2) ? 1 : 2;
    const float* A = (MODE == 1) ? g_h1 : g_ln;
    int m0 = blockIdx.x * 128;
    __shared__ __align__(16) float As[2][128][20];
    int t = threadIdx.x;
    int wid = t >> 5, wm = wid & 1, wn = wid >> 1;
    int ar_ = t >> 1, ac_ = (t & 1) * 8;
    FragC acc[4][NF];
    #pragma unroll
    for (int f = 0; f < 4; f++)
        #pragma unroll
        for (int j = 0; j < NF; j++) wmma::fill_fragment(acc[f][j], 0.f);
    float4 a0 = *(const float4*)(A + (size_t)(m0+ar_)*D_ + ac_);
    float4 a1 = *(const float4*)(A + (size_t)(m0+ar_)*D_ + ac_ + 4);
    if (MODE == 2) {
        float4 c0 = *(const float4*)(g_ct + (size_t)(m0+ar_)*D_ + ac_);
        float4 c1 = *(const float4*)(g_ct + (size_t)(m0+ar_)*D_ + ac_ + 4);
        a0.x+=c0.x; a0.y+=c0.y; a0.z+=c0.z; a0.w+=c0.w;
        a1.x+=c1.x; a1.y+=c1.y; a1.z+=c1.z; a1.w+=c1.w;
    }
    *(float4*)&As[0][ar_][ac_]   = a0;
    *(float4*)&As[0][ar_][ac_+4] = a1;
    __syncthreads();
    const int nit = 8;
    for (int it = 0; it < nit; it++) {
        int cur = it & 1;
        if (it + 1 < nit) {
            int k0 = (it+1)*16;
            a0 = *(const float4*)(A + (size_t)(m0+ar_)*D_ + k0 + ac_);
            a1 = *(const float4*)(A + (size_t)(m0+ar_)*D_ + k0 + ac_ + 4);
            if (MODE == 2) {
                float4 c0 = *(const float4*)(g_ct + (size_t)(m0+ar_)*D_ + k0 + ac_);
                float4 c1 = *(const float4*)(g_ct + (size_t)(m0+ar_)*D_ + k0 + ac_ + 4);
                a0.x+=c0.x; a0.y+=c0.y; a0.z+=c0.z; a0.w+=c0.w;
                a1.x+=c1.x; a1.y+=c1.y; a1.z+=c1.z; a1.w+=c1.w;
            }
        }
        #pragma unroll
        for (int ks = 0; ks < 16; ks += 8) {
            int kk = it*16 + ks;
            FragBr bf[NF];
            #pragma unroll
            for (int j = 0; j < NF; j++) {
                wmma::load_matrix_sync(bf[j], Wm + (size_t)kk*NOUT + wn*(16*NF) + j*16, NOUT);
                cvt_tf32(bf[j]);
            }
            #pragma unroll
            for (int f = 0; f < 4; f++) {
                FragAr af;
                wmma::load_matrix_sync(af, &As[cur][wm*64 + f*16][ks], 20);
                cvt_tf32(af);
                #pragma unroll
                for (int j = 0; j < NF; j++) wmma::mma_sync(acc[f][j], af, bf[j], acc[f][j]);
            }
        }
        if (it + 1 < nit) {
            int nx = cur ^ 1;
            *(float4*)&As[nx][ar_][ac_]   = a0;
            *(float4*)&As[nx][ar_][ac_+4] = a1;
            __syncthreads();
        }
    }
    if (MODE == 2) {
        int b = m0 / S_, s0 = m0 % S_;
        float* ob = outp + (size_t)b*C_*S_ + s0;
        #pragma unroll
        for (int f = 0; f < 4; f++)
            wmma::store_matrix_sync(ob + (size_t)(wn*16)*S_ + wm*64 + f*16,
                                    acc[f][0], S_, wmma::mem_col_major);
    } else {
        float* dst = (MODE == 0) ? g_h1 : g_ln;
        #pragma unroll
        for (int f = 0; f < 4; f++)
            #pragma unroll
            for (int j = 0; j < NF; j++) {
                if (MODE == 0) {
                    #pragma unroll
                    for (int e = 0; e < acc[f][j].num_elements; e++)
                        acc[f][j].x[e] = fmaxf(acc[f][j].x[e], 0.f);
                }
                wmma::store_matrix_sync(dst + (size_t)(m0 + wm*64 + f*16)*D_ + wn*32 + j*16,
                                        acc[f][j], D_, wmma::mem_row_major);
            }
    }
}

// ---------------- launch ----------------
extern "C" void kernel_launch(void* const* d_in, const int* in_sizes, int n_in,
                              void* d_out, int out_size) {
    const float* x_lf = (const float*)d_in[0];
    const float* x_hf = (const float*)d_in[1];
    const float* W_in = (const float*)d_in[2];
    const float* W_kv = (const float*)d_in[3];
    const float* ln_g = (const float*)d_in[4];
    const float* ln_b = (const float*)d_in[5];
    const float* W_m1 = (const float*)d_in[6];
    const float* W_m2 = (const float*)d_in[7];
    const float* W_ot = (const float*)d_in[8];
    float* out = (float*)d_out;

    k_tokens_wmma<0><<<NPOS_/128, 256>>>(x_hf, W_in);
    k_tokens_wmma<1><<<NPOS_/128, 256>>>(x_lf, W_kv);

    // sf attention
    k_fold<0><<<dim3(B_*M_SF, 2), 256>>>();
    k_score_sf<<<dim3(M_SF/64, M_SF/128, B_), 256>>>();
    k_softmax_sf<<<B_*M_SF, 256>>>();
    k_pv_sf<<<dim3((K_SF+63)/64, M_SF/128, B_), 256>>>();

    // af attention (split-K 8)
    k_fold<1><<<dim3(B_*M_AF, 2), 256>>>();
    k_score_small<1><<<dim3(3, 3, B_*8), 256>>>();
    k_softmax_small<1><<<B_*M_AF, 256>>>();
    k_pv<1><<<dim3(K_AF/64, 3, B_), 256>>>();

    // sa attention (split-K 16)
    k_fold<2><<<dim3(B_*M_SA, 2), 256>>>();
    k_score_small<2><<<dim3(3, 3, B_*16), 256>>>();
    k_softmax_small<2><<<B_*M_SA, 256>>>();
    k_pv<2><<<dim3(K_SA/64, 3, B_), 256>>>();

    // fused combine+LN, then MLP
    k_combine_ln<<<NPOS_/2, 256>>>(ln_g, ln_b);
    k_mlp_wmma<0><<<NPOS_/128, 256>>>(W_m1, nullptr);
    k_mlp_wmma<1><<<NPOS_/128, 256>>>(W_m2, nullptr);
    k_mlp_wmma<2><<<NPOS_/128, 256>>>(W_ot, out);
}

// round 9
// speedup vs baseline: 2.2826x; 1.0322x over previous
#include <cuda_runtime.h>
#include <mma.h>
using namespace nvcuda;

// ---------------- problem constants ----------------
#define B_    4
#define C_    64
#define NA_   25
#define D_    128
#define H_    32
#define W_    32
#define S_    25600      // NA*H*W
#define NPOS_ 102400     // B*S
#define M_SF  1024
#define K_SF  800
#define M_AF  160
#define K_AF  5120
#define M_SA  160
#define K_SA  10240
#define FOFF_ (16*B_*M_AF*M_AF)

// ---------------- scratch (device globals; no allocation) ----------------
__device__ float g_q [B_*D_*S_];
__device__ float g_kv[B_*D_*S_];

__device__ float g_sfQ[B_*M_SF*K_SF];
__device__ float g_sfK[B_*M_SF*K_SF];
__device__ float g_sfO[B_*M_SF*K_SF];
__device__ float g_afQ[B_*M_AF*K_AF];
__device__ float g_afK[B_*M_AF*K_AF];
__device__ float g_afO[B_*M_AF*K_AF];
__device__ float g_saQ[B_*M_SA*K_SA];
__device__ float g_saK[B_*M_SA*K_SA];
__device__ float g_saO[B_*M_SA*K_SA];

__device__ float g_ivq_sf[B_*M_SF];
__device__ float g_ivk_sf[B_*M_SF];
__device__ float g_ivq_af[B_*M_AF];
__device__ float g_ivk_af[B_*M_AF];
__device__ float g_ivq_sa[B_*M_SA];
__device__ float g_ivk_sa[B_*M_SA];

__device__ float g_att[B_*M_SF*M_SF];

__device__ float g_ct[NPOS_*D_];
__device__ float g_ln[NPOS_*D_];
__device__ float g_h1[NPOS_*D_];

// pre-rounded weights: [0]=W_in(8192) [8192]=W_kv(8192) [16384]=W_m1(16384)
//                      [32768]=W_m2(16384) [49152]=W_out(8192)
__device__ float g_wrk[57344];

__device__ __forceinline__ float tf32r(float x) {
    float y;
    asm("cvt.rna.tf32.f32 %0, %1;" : "=f"(y) : "f"(x));
    return y;
}

// ---------------- wmma tf32 types ----------------
using FragAr = wmma::fragment<wmma::matrix_a, 16,16,8, wmma::precision::tf32, wmma::row_major>;
using FragAc = wmma::fragment<wmma::matrix_a, 16,16,8, wmma::precision::tf32, wmma::col_major>;
using FragBr = wmma::fragment<wmma::matrix_b, 16,16,8, wmma::precision::tf32, wmma::row_major>;
using FragBc = wmma::fragment<wmma::matrix_b, 16,16,8, wmma::precision::tf32, wmma::col_major>;
using FragC  = wmma::fragment<wmma::accumulator, 16,16,8, float>;

template<class F> __device__ __forceinline__ void cvt_tf32(F& f) {
    #pragma unroll
    for (int i = 0; i < f.num_elements; i++) f.x[i] = wmma::__float_to_tf32(f.x[i]);
}

// ---------------- 0) pre-round all weights into g_wrk ----------------
__global__ void k_roundw(const float* __restrict__ Win, const float* __restrict__ Wkv,
                         const float* __restrict__ Wm1, const float* __restrict__ Wm2,
                         const float* __restrict__ Wot) {
    int i = blockIdx.x*256 + threadIdx.x;
    if (i >= 57344) return;
    const float* src;
    int off;
    if (i < 8192)       { src = Win; off = 0; }
    else if (i < 16384) { src = Wkv; off = 8192; }
    else if (i < 32768) { src = Wm1; off = 16384; }
    else if (i < 49152) { src = Wm2; off = 32768; }
    else                { src = Wot; off = 49152; }
    g_wrk[i] = tf32r(src[i - off]);
}

// ===================================================================
// 1) token projection: y[(b,dc),s] = sum_c x[(b,c),s] * W[c,dc]
// ===================================================================
template<int WHICH>
__global__ __launch_bounds__(256) void k_tokens_wmma(const float* __restrict__ x) {
    const float* Wm = g_wrk + (WHICH == 0 ? 0 : 8192);
    float* y = (WHICH == 0) ? g_q : g_kv;
    int m0 = blockIdx.x * 128;
    int b = m0 / S_, s0 = m0 % S_;
    const float* xb = x + (size_t)b*C_*S_ + s0;
    int wid = threadIdx.x >> 5, wm = wid & 1, wn = wid >> 1;
    FragC acc[4][2];
    #pragma unroll
    for (int f = 0; f < 4; f++)
        #pragma unroll
        for (int j = 0; j < 2; j++) wmma::fill_fragment(acc[f][j], 0.f);
    for (int k = 0; k < C_; k += 8) {
        FragBr bf[2];
        #pragma unroll
        for (int j = 0; j < 2; j++)
            wmma::load_matrix_sync(bf[j], Wm + (size_t)k*D_ + wn*32 + j*16, D_);
        #pragma unroll
        for (int f = 0; f < 4; f++) {
            FragAc af;
            wmma::load_matrix_sync(af, xb + (size_t)k*S_ + wm*64 + f*16, S_);
            cvt_tf32(af);
            #pragma unroll
            for (int j = 0; j < 2; j++) wmma::mma_sync(acc[f][j], af, bf[j], acc[f][j]);
        }
    }
    float* yb = y + (size_t)b*D_*S_ + s0;
    #pragma unroll
    for (int f = 0; f < 4; f++)
        #pragma unroll
        for (int j = 0; j < 2; j++)
            wmma::store_matrix_sync(yb + (size_t)(wn*32 + j*16)*S_ + wm*64 + f*16,
                                    acc[f][j], S_, wmma::mem_col_major);
}

// ---------------- 2) fold gather + inverse L2 norms (tf32-rounded output) ----------------
template<int TYPE>
__global__ void k_fold() {
    constexpr int MM  = TYPE==0 ? M_SF : (TYPE==1 ? M_AF : M_SA);
    constexpr int KK  = TYPE==0 ? K_SF : (TYPE==1 ? K_AF : K_SA);
    constexpr int OFF = TYPE==0 ? 0 : (TYPE==1 ? 32 : 64);
    int row = blockIdx.x;
    int isK = blockIdx.y;
    int b = row / MM, m = row % MM;
    const float* src = isK ? g_kv : g_q;
    float* dst; float* ivd;
    if (TYPE==0) { dst = isK ? g_sfK : g_sfQ; ivd = isK ? g_ivk_sf : g_ivq_sf; }
    else if (TYPE==1) { dst = isK ? g_afK : g_afQ; ivd = isK ? g_ivk_af : g_ivq_af; }
    else { dst = isK ? g_saK : g_saQ; ivd = isK ? g_ivk_sa : g_ivq_sa; }
    const float* base = src + ((size_t)b*D_ + OFF)*S_;
    float* drow = dst + (size_t)row*KK;
    int t = threadIdx.x;
    float ss = 0.f;
    if (TYPE == 0) {
        int ch = m >> 5, hh = m & 31;
        const float* bp = base + (size_t)ch*S_ + hh*W_;
        for (int kk = t; kk < KK; kk += 256) {
            int n = kk >> 5, ww = kk & 31;
            float v = tf32r(bp[n*(H_*W_) + ww]);
            drow[kk] = v;
            ss += v*v;
        }
    } else if (TYPE == 1) {
        int ch = m / 5, uu = m % 5;
        const float* bp = base + (size_t)ch*S_;
        for (int k = t; k < KK; k += 256) {
            int hh = k / 160, vv = (k >> 5) % 5, ww = k & 31;
            int n = uu*5 + vv;
            float v = tf32r(bp[n*(H_*W_) + hh*W_ + ww]);
            drow[k] = v;
            ss += v*v;
        }
    } else {
        int hh = m / 5, uu = m % 5;
        for (int k = t; k < KK; k += 256) {
            int ch = k / 160, vv = (k >> 5) % 5, ww = k & 31;
            int n = uu*5 + vv;
            float v = tf32r(base[(size_t)ch*S_ + n*(H_*W_) + hh*W_ + ww]);
            drow[k] = v;
            ss += v*v;
        }
    }
    __shared__ float red[256];
    red[t] = ss; __syncthreads();
    for (int st = 128; st > 0; st >>= 1) { if (t < st) red[t] += red[t + st]; __syncthreads(); }
    if (t == 0) ivd[row] = 1.f / fmaxf(sqrtf(red[0]), 1e-12f);
}

// ===================================================================
// 3a) SF raw scores (NT), wmma tf32, inputs pre-rounded (no cvt)
// ===================================================================
__global__ __launch_bounds__(256) void k_score_sf() {
    int b = blockIdx.z, m0 = blockIdx.y*128, n0 = blockIdx.x*64;
    if (n0 > m0 + 127) return;
    const float* Ab = g_sfQ + (size_t)b*M_SF*K_SF;
    const float* Bb = g_sfK + (size_t)b*M_SF*K_SF;
    __shared__ __align__(16) float As[2][128][20];
    __shared__ __align__(16) float Bs[2][64][20];
    int t = threadIdx.x;
    int wid = t >> 5, wm = wid & 1, wn = wid >> 1;
    int ar_ = t >> 1, ac_ = (t & 1) * 8;
    int br_ = t >> 2, bc_ = (t & 3) * 4;
    FragC acc[4];
    #pragma unroll
    for (int i = 0; i < 4; i++) wmma::fill_fragment(acc[i], 0.f);
    float4 a0 = *(const float4*)(Ab + (size_t)(m0+ar_)*K_SF + ac_);
    float4 a1 = *(const float4*)(Ab + (size_t)(m0+ar_)*K_SF + ac_ + 4);
    float4 b0 = *(const float4*)(Bb + (size_t)(n0+br_)*K_SF + bc_);
    *(float4*)&As[0][ar_][ac_]   = a0;
    *(float4*)&As[0][ar_][ac_+4] = a1;
    *(float4*)&Bs[0][br_][bc_]   = b0;
    __syncthreads();
    const int nit = K_SF/16;
    for (int it = 0; it < nit; it++) {
        int cur = it & 1;
        if (it + 1 < nit) {
            int k0 = (it+1)*16;
            a0 = *(const float4*)(Ab + (size_t)(m0+ar_)*K_SF + k0 + ac_);
            a1 = *(const float4*)(Ab + (size_t)(m0+ar_)*K_SF + k0 + ac_ + 4);
            b0 = *(const float4*)(Bb + (size_t)(n0+br_)*K_SF + k0 + bc_);
        }
        #pragma unroll
        for (int ks = 0; ks < 16; ks += 8) {
            FragBc bf;
            wmma::load_matrix_sync(bf, &Bs[cur][wn*16][ks], 20);
            #pragma unroll
            for (int f = 0; f < 4; f++) {
                FragAr af;
                wmma::load_matrix_sync(af, &As[cur][wm*64 + f*16][ks], 20);
                wmma::mma_sync(acc[f], af, bf, acc[f]);
            }
        }
        if (it + 1 < nit) {
            int nx = cur ^ 1;
            *(float4*)&As[nx][ar_][ac_]   = a0;
            *(float4*)&As[nx][ar_][ac_+4] = a1;
            *(float4*)&Bs[nx][br_][bc_]   = b0;
            __syncthreads();
        }
    }
    float* att = g_att + (size_t)b*M_SF*M_SF;
    #pragma unroll
    for (int f = 0; f < 4; f++)
        wmma::store_matrix_sync(att + (size_t)(m0 + wm*64 + f*16)*M_SF + n0 + wn*16,
                                acc[f], M_SF, wmma::mem_row_major);
}

// ===================================================================
// 4a) SF softmax (scale + mask + softmax); writes tf32-rounded probs
// ===================================================================
__global__ __launch_bounds__(256) void k_softmax_sf() {
    int blk = blockIdx.x;
    int b = blk >> 10, m = blk & 1023;
    float* p = g_att + ((size_t)b*M_SF + m)*M_SF;
    int LIMW = ((m >> 7) + 1) << 7;
    float qn = g_ivq_sf[b*M_SF + m];
    const float* ivk = g_ivk_sf + b*M_SF;
    int t = threadIdx.x;
    __shared__ float red[256];
    float vv[4];
    float mx = -3.4e38f;
    #pragma unroll
    for (int i = 0; i < 4; i++) {
        int k = t + i*256;
        if (k < LIMW) {
            float v = (k <= m) ? p[k]*qn*ivk[k] : -3.4e38f;
            vv[i] = v; mx = fmaxf(mx, v);
        }
    }
    red[t] = mx; __syncthreads();
    for (int st = 128; st > 0; st >>= 1) { if (t < st) red[t] = fmaxf(red[t], red[t+st]); __syncthreads(); }
    mx = red[0]; __syncthreads();
    float s = 0.f;
    #pragma unroll
    for (int i = 0; i < 4; i++) {
        int k = t + i*256;
        if (k < LIMW) {
            float e = (k <= m) ? expf(vv[i] - mx) : 0.f;
            vv[i] = e; s += e;
        }
    }
    red[t] = s; __syncthreads();
    for (int st = 128; st > 0; st >>= 1) { if (t < st) red[t] += red[t+st]; __syncthreads(); }
    float inv = 1.f / red[0];
    #pragma unroll
    for (int i = 0; i < 4; i++) {
        int k = t + i*256;
        if (k < LIMW) p[k] = tf32r(vv[i]*inv);
    }
}

// ===================================================================
// 5a) SF O = P @ V (NN), wmma tf32, inputs pre-rounded (no cvt)
// ===================================================================
__global__ __launch_bounds__(256) void k_pv_sf() {
    int b = blockIdx.z, m0 = blockIdx.y*128, k0 = blockIdx.x*64;
    const float* Pb = g_att + (size_t)b*M_SF*M_SF;
    const float* Vb = g_sfK + (size_t)b*M_SF*K_SF;
    __shared__ __align__(16) float As[2][128][20];
    __shared__ __align__(16) float Bs[2][16][68];
    int t = threadIdx.x;
    int wid = t >> 5, wm = wid & 1, wn = wid >> 1;
    int ar_ = t >> 1, ac_ = (t & 1) * 8;
    int vr_ = t >> 4, vc_ = (t & 15) * 4;
    bool bok = (k0 + vc_) < K_SF;
    FragC acc[4];
    #pragma unroll
    for (int i = 0; i < 4; i++) wmma::fill_fragment(acc[i], 0.f);
    float4 a0 = *(const float4*)(Pb + (size_t)(m0+ar_)*M_SF + ac_);
    float4 a1 = *(const float4*)(Pb + (size_t)(m0+ar_)*M_SF + ac_ + 4);
    float4 b0 = bok ? *(const float4*)(Vb + (size_t)vr_*K_SF + k0 + vc_) : make_float4(0,0,0,0);
    *(float4*)&As[0][ar_][ac_]   = a0;
    *(float4*)&As[0][ar_][ac_+4] = a1;
    *(float4*)&Bs[0][vr_][vc_]   = b0;
    __syncthreads();
    const int nit = (m0 + 128) / 16;
    for (int it = 0; it < nit; it++) {
        int cur = it & 1;
        if (it + 1 < nit) {
            int n0 = (it+1)*16;
            a0 = *(const float4*)(Pb + (size_t)(m0+ar_)*M_SF + n0 + ac_);
            a1 = *(const float4*)(Pb + (size_t)(m0+ar_)*M_SF + n0 + ac_ + 4);
            b0 = bok ? *(const float4*)(Vb + (size_t)(n0+vr_)*K_SF + k0 + vc_) : make_float4(0,0,0,0);
        }
        #pragma unroll
        for (int ks = 0; ks < 16; ks += 8) {
            FragBr bf;
            wmma::load_matrix_sync(bf, &Bs[cur][ks][wn*16], 68);
            #pragma unroll
            for (int f = 0; f < 4; f++) {
                FragAr af;
                wmma::load_matrix_sync(af, &As[cur][wm*64 + f*16][ks], 20);
                wmma::mma_sync(acc[f], af, bf, acc[f]);
            }
        }
        if (it + 1 < nit) {
            int nx = cur ^ 1;
            *(float4*)&As[nx][ar_][ac_]   = a0;
            *(float4*)&As[nx][ar_][ac_+4] = a1;
            *(float4*)&Bs[nx][vr_][vc_]   = b0;
            __syncthreads();
        }
    }
    float* O = g_sfO + (size_t)b*M_SF*K_SF;
    int col0 = k0 + wn*16;
    if (col0 < K_SF) {
        #pragma unroll
        for (int f = 0; f < 4; f++)
            wmma::store_matrix_sync(O + (size_t)(m0 + wm*64 + f*16)*K_SF + col0,
                                    acc[f], K_SF, wmma::mem_row_major);
    }
}

// ===================================================================
// 3b) af/sa raw scores, split-K (SIMT)
// ===================================================================
template<int TYPE>
__global__ __launch_bounds__(256) void k_score_small() {
    constexpr int MM = 160;
    constexpr int KK = TYPE==1 ? K_AF : K_SA;
    constexpr int CH = TYPE==1 ? 8 : 16;
    constexpr int CHK = KK / CH;
    const float* Qf = TYPE==1 ? g_afQ : g_saQ;
    const float* Kf = TYPE==1 ? g_afK : g_saK;
    int z = blockIdx.z;
    int b = z / CH, ch = z % CH;
    int m0 = blockIdx.y*64, n0 = blockIdx.x*64;
    if (n0 > m0 + 63) return;
    const float* Ab = Qf + (size_t)b*MM*KK;
    const float* Bb = Kf + (size_t)b*MM*KK;
    __shared__ __align__(16) float As[16][64];
    __shared__ __align__(16) float Bs[16][64];
    int t = threadIdx.x, tn = t & 15, tm = t >> 4;
    int lr = t >> 2, lc = (t & 3) << 2;
    float acc[4][4] = {};
    int kbeg = ch*CHK, kend = kbeg + CHK;
    for (int k0 = kbeg; k0 < kend; k0 += 16) {
        float4 av = make_float4(0,0,0,0), bv = make_float4(0,0,0,0);
        if (m0 + lr < MM) av = *(const float4*)(Ab + (size_t)(m0+lr)*KK + k0 + lc);
        if (n0 + lr < MM) bv = *(const float4*)(Bb + (size_t)(n0+lr)*KK + k0 + lc);
        __syncthreads();
        As[lc+0][lr]=av.x; As[lc+1][lr]=av.y; As[lc+2][lr]=av.z; As[lc+3][lr]=av.w;
        Bs[lc+0][lr]=bv.x; Bs[lc+1][lr]=bv.y; Bs[lc+2][lr]=bv.z; Bs[lc+3][lr]=bv.w;
        __syncthreads();
        #pragma unroll
        for (int kk = 0; kk < 16; kk++) {
            float4 a = *(const float4*)&As[kk][tm << 2];
            float4 bq = *(const float4*)&Bs[kk][tn << 2];
            acc[0][0]+=a.x*bq.x; acc[0][1]+=a.x*bq.y; acc[0][2]+=a.x*bq.z; acc[0][3]+=a.x*bq.w;
            acc[1][0]+=a.y*bq.x; acc[1][1]+=a.y*bq.y; acc[1][2]+=a.y*bq.z; acc[1][3]+=a.y*bq.w;
            acc[2][0]+=a.z*bq.x; acc[2][1]+=a.z*bq.y; acc[2][2]+=a.z*bq.z; acc[2][3]+=a.z*bq.w;
            acc[3][0]+=a.w*bq.x; acc[3][1]+=a.w*bq.y; acc[3][2]+=a.w*bq.z; acc[3][3]+=a.w*bq.w;
        }
    }
    float* part = g_att + ((size_t)(ch*B_ + b)*MM)*MM;
    #pragma unroll
    for (int i = 0; i < 4; i++) {
        int m = m0 + (tm<<2) + i; if (m >= MM) continue;
        #pragma unroll
        for (int j = 0; j < 4; j++) {
            int n = n0 + (tn<<2) + j; if (n >= MM) continue;
            part[(size_t)m*MM + n] = acc[i][j];
        }
    }
}

// ---------------- 4b) af/sa softmax over split-K partials ----------------
template<int TYPE>
__global__ __launch_bounds__(256) void k_softmax_small() {
    constexpr int MM = 160;
    constexpr int CH = TYPE==1 ? 8 : 16;
    const float* ivq = TYPE==1 ? g_ivq_af : g_ivq_sa;
    const float* ivk = TYPE==1 ? g_ivk_af : g_ivk_sa;
    int blk = blockIdx.x;
    int b = blk / MM, m = blk % MM;
    int t = threadIdx.x;
    float v = -3.4e38f;
    if (t < MM && t <= m) {
        float s = 0.f;
        #pragma unroll 4
        for (int ch = 0; ch < CH; ch++)
            s += g_att[(((size_t)(ch*B_ + b))*MM + m)*MM + t];
        v = s * ivq[b*MM + m] * ivk[b*MM + t];
    }
    __shared__ float red[256];
    red[t] = v; __syncthreads();
    for (int st = 128; st > 0; st >>= 1) { if (t < st) red[t] = fmaxf(red[t], red[t+st]); __syncthreads(); }
    float mx = red[0]; __syncthreads();
    float e = (t < MM && t <= m) ? expf(v - mx) : 0.f;
    red[t] = e; __syncthreads();
    for (int st = 128; st > 0; st >>= 1) { if (t < st) red[t] += red[t+st]; __syncthreads(); }
    float inv = 1.f / red[0];
    if (t < MM) g_att[FOFF_ + ((size_t)b*MM + m)*MM + t] = e*inv;
}

// ---------------- 5b) af/sa O = P @ V (SIMT) ----------------
template<int TYPE>
__global__ __launch_bounds__(256) void k_pv() {
    constexpr int MM = 160;
    constexpr int KK = TYPE==1 ? K_AF : K_SA;
    const float* V = TYPE==1 ? g_afK : g_saK;
    float* O = TYPE==1 ? g_afO : g_saO;
    int b = blockIdx.z, m0 = blockIdx.y*64, k0 = blockIdx.x*64;
    int t = threadIdx.x, tn = t & 15, tm = t >> 4;
    const float* Pb = g_att + FOFF_ + (size_t)b*MM*MM;
    const float* Vb = V + (size_t)b*MM*KK;
    __shared__ __align__(16) float As[16][64];
    __shared__ __align__(16) float Bs[16][64];
    int lr = t >> 2, lc = (t & 3) << 2;
    int br = t >> 4, bc = (t & 15) << 2;
    float acc[4][4] = {};
    int NLIM = (m0 + 64 < MM) ? m0 + 64 : MM;
    for (int n0 = 0; n0 < NLIM; n0 += 16) {
        float4 av = make_float4(0,0,0,0), bv = make_float4(0,0,0,0);
        if (m0 + lr < MM) av = *(const float4*)(Pb + (size_t)(m0+lr)*MM + n0 + lc);
        if (n0 + br < MM) bv = *(const float4*)(Vb + (size_t)(n0+br)*KK + k0 + bc);
        __syncthreads();
        As[lc+0][lr]=av.x; As[lc+1][lr]=av.y; As[lc+2][lr]=av.z; As[lc+3][lr]=av.w;
        *(float4*)&Bs[br][bc] = bv;
        __syncthreads();
        #pragma unroll
        for (int nn = 0; nn < 16; nn++) {
            float4 a = *(const float4*)&As[nn][tm << 2];
            float4 bq = *(const float4*)&Bs[nn][tn << 2];
            acc[0][0]+=a.x*bq.x; acc[0][1]+=a.x*bq.y; acc[0][2]+=a.x*bq.z; acc[0][3]+=a.x*bq.w;
            acc[1][0]+=a.y*bq.x; acc[1][1]+=a.y*bq.y; acc[1][2]+=a.y*bq.z; acc[1][3]+=a.y*bq.w;
            acc[2][0]+=a.z*bq.x; acc[2][1]+=a.z*bq.y; acc[2][2]+=a.z*bq.z; acc[2][3]+=a.z*bq.w;
            acc[3][0]+=a.w*bq.x; acc[3][1]+=a.w*bq.y; acc[3][2]+=a.w*bq.z; acc[3][3]+=a.w*bq.w;
        }
    }
    #pragma unroll
    for (int i = 0; i < 4; i++) {
        int m = m0 + (tm<<2) + i; if (m >= MM) continue;
        #pragma unroll
        for (int j = 0; j < 4; j++) {
            int k = k0 + (tn<<2) + j;
            O[((size_t)b*MM + m)*KK + k] = acc[i][j];
        }
    }
}

// ===================================================================
// 6+7) fused unfold+residual+LayerNorm (ln output tf32-rounded)
// ===================================================================
__global__ __launch_bounds__(256) void k_combine_ln(const float* __restrict__ gamma,
                                                    const float* __restrict__ beta) {
    int t = threadIdx.x;
    int tok = t >> 7;
    int dc = t & 127;
    int T = blockIdx.x*2 + tok;
    int ww = T & 31, hh = (T >> 5) & 31;
    int bn = T >> 10;
    int b = bn / 25, n = bn % 25;
    int uu = n / 5, vv = n % 5;
    float r = g_kv[((size_t)b*D_ + dc)*S_ + n*(H_*W_) + hh*W_ + ww];
    float o;
    if (dc < 32) {
        int m = dc*32 + hh, k = n*32 + ww;
        o = g_sfO[((size_t)b*M_SF + m)*K_SF + k];
    } else if (dc < 64) {
        int m = (dc-32)*5 + uu, k = (hh*5 + vv)*32 + ww;
        o = g_afO[((size_t)b*M_AF + m)*K_AF + k];
    } else {
        int m = hh*5 + uu, k = ((dc-64)*5 + vv)*32 + ww;
        o = g_saO[((size_t)b*M_SA + m)*K_SA + k];
    }
    float v = o + r;
    g_ct[(size_t)T*D_ + dc] = v;
    float s = v;
    #pragma unroll
    for (int of = 16; of > 0; of >>= 1) s += __shfl_xor_sync(0xffffffffu, s, of);
    __shared__ float wsum[2][4];
    int wg = (t >> 5) & 3;
    if ((t & 31) == 0) wsum[tok][wg] = s;
    __syncthreads();
    float mu = (wsum[tok][0]+wsum[tok][1]+wsum[tok][2]+wsum[tok][3]) * (1.f/128.f);
    float cx = v - mu;
    float sq = cx*cx;
    #pragma unroll
    for (int of = 16; of > 0; of >>= 1) sq += __shfl_xor_sync(0xffffffffu, sq, of);
    __shared__ float wsq[2][4];
    if ((t & 31) == 0) wsq[tok][wg] = sq;
    __syncthreads();
    float var = (wsq[tok][0]+wsq[tok][1]+wsq[tok][2]+wsq[tok][3]) * (1.f/128.f);
    float inv = rsqrtf(var + 1e-5f);
    g_ln[(size_t)T*D_ + dc] = tf32r(cx*inv*gamma[dc] + beta[dc]);
}

// ===================================================================
// 8) MLP gemms, wmma tf32. A/B pre-rounded (cvt only for MODE2 sum at staging).
// MODE 0: h1 = relu(ln@W_m1) [h1 rounded]  MODE 1: ln <- h1@W_m2 (unrounded)
// MODE 2: out = round(ln+ct) @ W_out
// ===================================================================
template<int MODE>
__global__ __launch_bounds__(256) void k_mlp_wmma(float* __restrict__ outp) {
    constexpr int NOUT = (MODE == 2) ? 64 : 128;
    constexpr int NF   = (MODE == 2) ? 1 : 2;
    const float* Wm = g_wrk + (MODE == 0 ? 16384 : (MODE == 1 ? 32768 : 49152));
    const float* A = (MODE == 1) ? g_h1 : g_ln;
    int m0 = blockIdx.x * 128;
    __shared__ __align__(16) float As[2][128][20];
    int t = threadIdx.x;
    int wid = t >> 5, wm = wid & 1, wn = wid >> 1;
    int ar_ = t >> 1, ac_ = (t & 1) * 8;
    FragC acc[4][NF];
    #pragma unroll
    for (int f = 0; f < 4; f++)
        #pragma unroll
        for (int j = 0; j < NF; j++) wmma::fill_fragment(acc[f][j], 0.f);
    float4 a0 = *(const float4*)(A + (size_t)(m0+ar_)*D_ + ac_);
    float4 a1 = *(const float4*)(A + (size_t)(m0+ar_)*D_ + ac_ + 4);
    if (MODE == 2) {
        float4 c0 = *(const float4*)(g_ct + (size_t)(m0+ar_)*D_ + ac_);
        float4 c1 = *(const float4*)(g_ct + (size_t)(m0+ar_)*D_ + ac_ + 4);
        a0.x=tf32r(a0.x+c0.x); a0.y=tf32r(a0.y+c0.y); a0.z=tf32r(a0.z+c0.z); a0.w=tf32r(a0.w+c0.w);
        a1.x=tf32r(a1.x+c1.x); a1.y=tf32r(a1.y+c1.y); a1.z=tf32r(a1.z+c1.z); a1.w=tf32r(a1.w+c1.w);
    }
    *(float4*)&As[0][ar_][ac_]   = a0;
    *(float4*)&As[0][ar_][ac_+4] = a1;
    __syncthreads();
    const int nit = 8;
    for (int it = 0; it < nit; it++) {
        int cur = it & 1;
        if (it + 1 < nit) {
            int k0 = (it+1)*16;
            a0 = *(const float4*)(A + (size_t)(m0+ar_)*D_ + k0 + ac_);
            a1 = *(const float4*)(A + (size_t)(m0+ar_)*D_ + k0 + ac_ + 4);
            if (MODE == 2) {
                float4 c0 = *(const float4*)(g_ct + (size_t)(m0+ar_)*D_ + k0 + ac_);
                float4 c1 = *(const float4*)(g_ct + (size_t)(m0+ar_)*D_ + k0 + ac_ + 4);
                a0.x=tf32r(a0.x+c0.x); a0.y=tf32r(a0.y+c0.y); a0.z=tf32r(a0.z+c0.z); a0.w=tf32r(a0.w+c0.w);
                a1.x=tf32r(a1.x+c1.x); a1.y=tf32r(a1.y+c1.y); a1.z=tf32r(a1.z+c1.z); a1.w=tf32r(a1.w+c1.w);
            }
        }
        #pragma unroll
        for (int ks = 0; ks < 16; ks += 8) {
            int kk = it*16 + ks;
            FragBr bf[NF];
            #pragma unroll
            for (int j = 0; j < NF; j++)
                wmma::load_matrix_sync(bf[j], Wm + (size_t)kk*NOUT + wn*(16*NF) + j*16, NOUT);
            #pragma unroll
            for (int f = 0; f < 4; f++) {
                FragAr af;
                wmma::load_matrix_sync(af, &As[cur][wm*64 + f*16][ks], 20);
                #pragma unroll
                for (int j = 0; j < NF; j++) wmma::mma_sync(acc[f][j], af, bf[j], acc[f][j]);
            }
        }
        if (it + 1 < nit) {
            int nx = cur ^ 1;
            *(float4*)&As[nx][ar_][ac_]   = a0;
            *(float4*)&As[nx][ar_][ac_+4] = a1;
            __syncthreads();
        }
    }
    if (MODE == 2) {
        int b = m0 / S_, s0 = m0 % S_;
        float* ob = outp + (size_t)b*C_*S_ + s0;
        #pragma unroll
        for (int f = 0; f < 4; f++)
            wmma::store_matrix_sync(ob + (size_t)(wn*16)*S_ + wm*64 + f*16,
                                    acc[f][0], S_, wmma::mem_col_major);
    } else {
        float* dst = (MODE == 0) ? g_h1 : g_ln;
        #pragma unroll
        for (int f = 0; f < 4; f++)
            #pragma unroll
            for (int j = 0; j < NF; j++) {
                if (MODE == 0) {
                    #pragma unroll
                    for (int e = 0; e < acc[f][j].num_elements; e++)
                        acc[f][j].x[e] = tf32r(fmaxf(acc[f][j].x[e], 0.f));
                }
                wmma::store_matrix_sync(dst + (size_t)(m0 + wm*64 + f*16)*D_ + wn*32 + j*16,
                                        acc[f][j], D_, wmma::mem_row_major);
            }
    }
}

// ---------------- launch ----------------
extern "C" void kernel_launch(void* const* d_in, const int* in_sizes, int n_in,
                              void* d_out, int out_size) {
    const float* x_lf = (const float*)d_in[0];
    const float* x_hf = (const float*)d_in[1];
    const float* W_in = (const float*)d_in[2];
    const float* W_kv = (const float*)d_in[3];
    const float* ln_g = (const float*)d_in[4];
    const float* ln_b = (const float*)d_in[5];
    const float* W_m1 = (const float*)d_in[6];
    const float* W_m2 = (const float*)d_in[7];
    const float* W_ot = (const float*)d_in[8];
    float* out = (float*)d_out;

    k_roundw<<<224, 256>>>(W_in, W_kv, W_m1, W_m2, W_ot);
    k_tokens_wmma<0><<<NPOS_/128, 256>>>(x_hf);
    k_tokens_wmma<1><<<NPOS_/128, 256>>>(x_lf);

    // sf attention
    k_fold<0><<<dim3(B_*M_SF, 2), 256>>>();
    k_score_sf<<<dim3(M_SF/64, M_SF/128, B_), 256>>>();
    k_softmax_sf<<<B_*M_SF, 256>>>();
    k_pv_sf<<<dim3((K_SF+63)/64, M_SF/128, B_), 256>>>();

    // af attention (split-K 8)
    k_fold<1><<<dim3(B_*M_AF, 2), 256>>>();
    k_score_small<1><<<dim3(3, 3, B_*8), 256>>>();
    k_softmax_small<1><<<B_*M_AF, 256>>>();
    k_pv<1><<<dim3(K_AF/64, 3, B_), 256>>>();

    // sa attention (split-K 16)
    k_fold<2><<<dim3(B_*M_SA, 2), 256>>>();
    k_score_small<2><<<dim3(3, 3, B_*16), 256>>>();
    k_softmax_small<2><<<B_*M_SA, 256>>>();
    k_pv<2><<<dim3(K_SA/64, 3, B_), 256>>>();

    // fused combine+LN, then MLP
    k_combine_ln<<<NPOS_/2, 256>>>(ln_g, ln_b);
    k_mlp_wmma<0><<<NPOS_/128, 256>>>(nullptr);
    k_mlp_wmma<1><<<NPOS_/128, 256>>>(nullptr);
    k_mlp_wmma<2><<<NPOS_/128, 256>>>(out);
}